// round 3
// baseline (speedup 1.0000x reference)
#include <cuda_runtime.h>

#define NB   2048
#define NT   512
#define NHID 1024
#define NVOC 31
#define EPS  1e-5f
#define NBLK 128

// ---- persistent device state (no allocations allowed) ----
__device__ __align__(16) float g_h[2][NB * NHID];   // ping-pong hidden state
__device__ __align__(16) float g_sum[NHID];
__device__ __align__(16) float g_sumsq[NHID];
__device__ __align__(16) float g_scale[NHID];
__device__ __align__(16) float g_shift[NHID];
__device__ unsigned g_count;

// ---------------------------------------------------------------------------
// init: zero h[0], BN accumulators, barrier counter
// ---------------------------------------------------------------------------
__global__ void k_init() {
    int i = blockIdx.x * blockDim.x + threadIdx.x;
    int stride = gridDim.x * blockDim.x;
    for (int idx = i; idx < NB * NHID; idx += stride) g_h[0][idx] = 0.f;
    if (i < NHID) { g_sum[i] = 0.f; g_sumsq[i] = 0.f; }
    if (i == 0) g_count = 0u;
}

// ---------------------------------------------------------------------------
// software grid barrier (all NBLK blocks resident: NBLK=128 < 148 SMs)
// ---------------------------------------------------------------------------
__device__ __forceinline__ void gridbar(unsigned& epoch) {
    __syncthreads();
    epoch += NBLK;
    if (threadIdx.x == 0) {
        __threadfence();
        atomicAdd(&g_count, 1u);
        while (*(volatile unsigned*)&g_count < epoch) { }
        __threadfence();
    }
    __syncthreads();
}

// ---------------------------------------------------------------------------
// persistent kernel: all T=512 steps
// ---------------------------------------------------------------------------
#define BM 128
#define BN 128
#define BK 16
#define CM 16      // rows per block in the output GEMM
#define CKT 64

__global__ __launch_bounds__(256) void k_persist(
    const int* __restrict__ x, const float* __restrict__ emb,
    const float* __restrict__ W, const float* __restrict__ bias,
    const float* __restrict__ Who, const float* __restrict__ bho,
    const float* __restrict__ gamma, const float* __restrict__ beta,
    float* __restrict__ out)
{
    __shared__ float As[BK][BM + 8];
    __shared__ float Bs[BK][BN + 8];
    __shared__ int   xs[BM];
    __shared__ float red[16][BM];
    __shared__ float hs[CM][CKT];
    __shared__ float ws[CKT][33];

    const int b   = blockIdx.x;
    const int tid = threadIdx.x;
    unsigned epoch = 0;

    const int n0 = (b & 7) * BN;    // 8 col-blocks
    const int m0 = (b >> 3) * BM;   // 16 row-blocks
    const int tm = tid >> 4;        // 0..15
    const int tn = tid & 15;        // 0..15

    for (int t = 0; t < NT; t++) {
        const int cur = t & 1;
        const float* __restrict__ hprev = g_h[cur];
        float* __restrict__ hnext = g_h[cur ^ 1];

        // ================= phase 1: main GEMM + relu + stats =================
        if (tid < BM) xs[tid] = x[(m0 + tid) * NT + t];
        __syncthreads();

        float acc[8][8];
#pragma unroll
        for (int i = 0; i < 8; i++)
#pragma unroll
            for (int j = 0; j < 8; j++) acc[i][j] = 0.f;

        for (int k0 = 0; k0 < NHID; k0 += BK) {
#pragma unroll
            for (int u = 0; u < 2; u++) {
                int idx = tid * 2 + u;
                int row = idx >> 2;
                int kq = (idx & 3) * 4;
                float4 hv = *(const float4*)&hprev[(m0 + row) * NHID + k0 + kq];
                float4 ev = *(const float4*)&emb[xs[row] * NHID + k0 + kq];
                As[kq + 0][row] = hv.x + ev.x;
                As[kq + 1][row] = hv.y + ev.y;
                As[kq + 2][row] = hv.z + ev.z;
                As[kq + 3][row] = hv.w + ev.w;
                float4 wv = *(const float4*)&W[(n0 + row) * NHID + k0 + kq];
                Bs[kq + 0][row] = wv.x;
                Bs[kq + 1][row] = wv.y;
                Bs[kq + 2][row] = wv.z;
                Bs[kq + 3][row] = wv.w;
            }
            __syncthreads();
#pragma unroll
            for (int kk = 0; kk < BK; kk++) {
                float a[8], bb[8];
#pragma unroll
                for (int i = 0; i < 8; i++) a[i] = As[kk][tm * 8 + i];
#pragma unroll
                for (int j = 0; j < 8; j++) bb[j] = Bs[kk][tn * 8 + j];
#pragma unroll
                for (int i = 0; i < 8; i++)
#pragma unroll
                    for (int j = 0; j < 8; j++)
                        acc[i][j] = fmaf(a[i], bb[j], acc[i][j]);
            }
            __syncthreads();
        }

        float bb[8];
#pragma unroll
        for (int j = 0; j < 8; j++) bb[j] = bias[n0 + tn * 8 + j];

        float csum[8], csq[8];
#pragma unroll
        for (int j = 0; j < 8; j++) { csum[j] = 0.f; csq[j] = 0.f; }

#pragma unroll
        for (int i = 0; i < 8; i++) {
            int row = m0 + tm * 8 + i;
            float v[8];
#pragma unroll
            for (int j = 0; j < 8; j++) {
                float val = acc[i][j] + bb[j];
                val = fmaxf(val, 0.f);
                v[j] = val;
                csum[j] += val;
                csq[j] = fmaf(val, val, csq[j]);
            }
            float4* dst = (float4*)&hnext[(size_t)row * NHID + n0 + tn * 8];
            dst[0] = make_float4(v[0], v[1], v[2], v[3]);
            dst[1] = make_float4(v[4], v[5], v[6], v[7]);
        }

        __syncthreads();
#pragma unroll
        for (int j = 0; j < 8; j++) red[tm][tn * 8 + j] = csum[j];
        __syncthreads();
        if (tid < BM) {
            float s = 0.f;
#pragma unroll
            for (int r = 0; r < 16; r++) s += red[r][tid];
            atomicAdd(&g_sum[n0 + tid], s);
        }
        __syncthreads();
#pragma unroll
        for (int j = 0; j < 8; j++) red[tm][tn * 8 + j] = csq[j];
        __syncthreads();
        if (tid < BM) {
            float s = 0.f;
#pragma unroll
            for (int r = 0; r < 16; r++) s += red[r][tid];
            atomicAdd(&g_sumsq[n0 + tid], s);
        }

        gridbar(epoch);

        // ================= phase 2: BN finalize (blocks 0..3) ================
        if (b < 4) {
            int k = b * 256 + tid;
            float mu = g_sum[k] * (1.f / NB);
            float var = g_sumsq[k] * (1.f / NB) - mu * mu;
            float rs = rsqrtf(var + EPS);
            float sc = rs * gamma[k];
            g_scale[k] = sc;
            g_shift[k] = beta[k] - mu * sc;
            g_sum[k] = 0.f;
            g_sumsq[k] = 0.f;
        }

        gridbar(epoch);

        // ================= phase 3: output GEMM (16 rows/block) ==============
        {
            const float* __restrict__ h = hnext;
            int om0 = b * CM;
            int v = tid & 31;
            int rg = tid >> 5;   // 0..7, 2 rows each

            float oacc[2] = {0.f, 0.f};

            for (int k0 = 0; k0 < NHID; k0 += CKT) {
                // stage normalized h: 16 rows x 64 k = 256 float4, 1/thread
                {
                    int row = tid >> 4;
                    int q = (tid & 15) * 4;
                    float4 hv = *(const float4*)&h[(om0 + row) * NHID + k0 + q];
                    float4 sv = *(const float4*)&g_scale[k0 + q];
                    float4 fv = *(const float4*)&g_shift[k0 + q];
                    hs[row][q + 0] = fmaf(hv.x, sv.x, fv.x);
                    hs[row][q + 1] = fmaf(hv.y, sv.y, fv.y);
                    hs[row][q + 2] = fmaf(hv.z, sv.z, fv.z);
                    hs[row][q + 3] = fmaf(hv.w, sv.w, fv.w);
                }
                for (int idx = tid; idx < CKT * 32; idx += 256) {
                    int kk = idx & (CKT - 1);
                    int vv = idx >> 6;
                    ws[kk][vv] = (vv < NVOC) ? Who[vv * NHID + k0 + kk] : 0.f;
                }
                __syncthreads();
#pragma unroll
                for (int kk = 0; kk < CKT; kk += 4) {
                    float w0 = ws[kk + 0][v];
                    float w1 = ws[kk + 1][v];
                    float w2 = ws[kk + 2][v];
                    float w3 = ws[kk + 3][v];
#pragma unroll
                    for (int r = 0; r < 2; r++) {
                        float4 hv = *(const float4*)&hs[rg * 2 + r][kk];
                        float s = fmaf(hv.x, w0, oacc[r]);
                        s = fmaf(hv.y, w1, s);
                        s = fmaf(hv.z, w2, s);
                        oacc[r] = fmaf(hv.w, w3, s);
                    }
                }
                __syncthreads();
            }

            if (v < NVOC) {
                float bv = bho[v];
#pragma unroll
                for (int r = 0; r < 2; r++) {
                    size_t row = om0 + rg * 2 + r;
                    out[row * (size_t)(NT * NVOC) + (size_t)t * NVOC + v] =
                        oacc[r] + bv;
                }
            }
        }
        // no barrier needed here: phase1(t+1) touches disjoint buffers, and
        // the gridbar after phase1(t+1) fences scale/shift + stats reuse.
    }
}

// ---------------------------------------------------------------------------
extern "C" void kernel_launch(void* const* d_in, const int* in_sizes, int n_in,
                              void* d_out, int out_size)
{
    const int*   x     = (const int*)d_in[0];
    const float* emb   = (const float*)d_in[1];
    const float* Whh   = (const float*)d_in[2];
    const float* bhh   = (const float*)d_in[3];
    const float* Who   = (const float*)d_in[4];
    const float* bho   = (const float*)d_in[5];
    const float* gamma = (const float*)d_in[6];
    const float* beta  = (const float*)d_in[7];
    float* out = (float*)d_out;

    k_init<<<1024, 256>>>();
    k_persist<<<NBLK, 256>>>(x, emb, Whh, bhh, Who, bho, gamma, beta, out);
}

// round 6
// speedup vs baseline: 2.0494x; 2.0494x over previous
#include <cuda_runtime.h>
#include <cuda_bf16.h>
#include <cstdint>

#define NB   2048
#define NT   512
#define NHID 1024
#define NVOC 31
#define EPS  1e-5f
#define NBLK 128

#define KCH     64                  // K per staged chunk (bf16)
#define NCHUNK  (NHID / KCH)        // 16
#define TILE16K 16384               // one 128x64 bf16 tile, 128B rows
#define BUFSZ   (4 * TILE16K)       // Ah, Al, Bh, Bl

// smem layout (dynamic)
#define OFF_XS   0                  // 128 ints            -> 512
#define OFF_HS   512                // 16*64 floats        -> 4608
#define OFF_WS   4608               // 64*33 floats        -> 13056
#define OFF_BUF  13312              // 128B aligned, 2 buffers
#define SMEM_TOTAL (OFF_BUF + 2 * BUFSZ)   // 144384

// ---- persistent device state ----
__device__ __align__(16) uint16_t g_hA[2][NB * NHID];   // h bf16 hi
__device__ __align__(16) uint16_t g_hB[2][NB * NHID];   // h bf16 lo
__device__ __align__(16) uint16_t g_Wh[NHID * NHID];    // W_hh bf16 hi
__device__ __align__(16) uint16_t g_Wl[NHID * NHID];    // W_hh bf16 lo
__device__ __align__(16) float    g_embW[NVOC * NHID];  // emb @ W^T + b_hh
__device__ __align__(16) float    g_sum[NHID];
__device__ __align__(16) float    g_sumsq[NHID];
__device__ __align__(16) float    g_scale[NHID];
__device__ __align__(16) float    g_shift[NHID];
__device__ unsigned g_count;

// ============================ PTX helpers ============================
__device__ __forceinline__ uint32_t smem_to_u32(const void* p) {
    uint32_t a;
    asm("{ .reg .u64 t; cvta.to.shared.u64 t, %1; cvt.u32.u64 %0, t; }"
        : "=r"(a) : "l"(p));
    return a;
}
#define CP16(dst, src) \
    asm volatile("cp.async.cg.shared.global [%0], [%1], 16;" \
                 :: "r"(dst), "l"(src) : "memory")
#define CP_COMMIT() asm volatile("cp.async.commit_group;" ::: "memory")
#define CP_WAIT(n)  asm volatile("cp.async.wait_group %0;" :: "n"(n) : "memory")

__device__ __forceinline__ void ldsm4(uint32_t* r, uint32_t addr) {
    asm volatile("ldmatrix.sync.aligned.m8n8.x4.shared.b16 {%0,%1,%2,%3}, [%4];"
                 : "=r"(r[0]), "=r"(r[1]), "=r"(r[2]), "=r"(r[3]) : "r"(addr));
}
__device__ __forceinline__ void mma16816(float* c, const uint32_t* a,
                                         uint32_t b0, uint32_t b1) {
    asm volatile(
        "mma.sync.aligned.m16n8k16.row.col.f32.bf16.bf16.f32 "
        "{%0,%1,%2,%3}, {%4,%5,%6,%7}, {%8,%9}, {%0,%1,%2,%3};"
        : "+f"(c[0]), "+f"(c[1]), "+f"(c[2]), "+f"(c[3])
        : "r"(a[0]), "r"(a[1]), "r"(a[2]), "r"(a[3]), "r"(b0), "r"(b1));
}

// ---------------------------------------------------------------------------
// init: zero h[0] hi/lo + stats; split W_hh; precompute embW = emb@W^T + b_hh
// ---------------------------------------------------------------------------
__global__ void k_init(const float* __restrict__ W, const float* __restrict__ emb,
                       const float* __restrict__ bhh) {
    int gid = blockIdx.x * blockDim.x + threadIdx.x;
    int stride = gridDim.x * blockDim.x;
    uint32_t* zA = (uint32_t*)g_hA[0];
    uint32_t* zB = (uint32_t*)g_hB[0];
    for (int i = gid; i < NB * NHID / 2; i += stride) { zA[i] = 0u; zB[i] = 0u; }
    for (int i = gid; i < NHID * NHID; i += stride) {
        float v = W[i];
        __nv_bfloat16 h = __float2bfloat16(v);
        g_Wh[i] = __bfloat16_as_ushort(h);
        g_Wl[i] = __bfloat16_as_ushort(__float2bfloat16(v - __bfloat162float(h)));
    }
    if (gid < NVOC * NHID) {
        int v = gid >> 10, n = gid & (NHID - 1);
        const float4* er = (const float4*)(emb + (size_t)v * NHID);
        const float4* wr = (const float4*)(W + (size_t)n * NHID);
        float s0 = 0.f, s1 = 0.f, s2 = 0.f, s3 = 0.f;
        for (int k = 0; k < NHID / 4; k++) {
            float4 e = er[k], w = wr[k];
            s0 = fmaf(e.x, w.x, s0); s1 = fmaf(e.y, w.y, s1);
            s2 = fmaf(e.z, w.z, s2); s3 = fmaf(e.w, w.w, s3);
        }
        g_embW[gid] = (s0 + s1) + (s2 + s3) + bhh[n];
    }
    if (gid < NHID) { g_sum[gid] = 0.f; g_sumsq[gid] = 0.f; }
    if (gid == 0) g_count = 0u;
}

// ---------------------------------------------------------------------------
// software grid barrier (all 128 blocks resident)
// ---------------------------------------------------------------------------
__device__ __forceinline__ void gridbar(unsigned& epoch) {
    __syncthreads();
    epoch += NBLK;
    if (threadIdx.x == 0) {
        __threadfence();
        atomicAdd(&g_count, 1u);
        while (*(volatile unsigned*)&g_count < epoch) { }
        __threadfence();
    }
    __syncthreads();
}

// stage one 64-K chunk: A(hi,lo) rows m0.., B(hi,lo) rows n0.., SW128 swizzle
__device__ __forceinline__ void stage_chunk(
    uint32_t dstbase, const uint16_t* __restrict__ hH,
    const uint16_t* __restrict__ hL, int m0, int n0, int k0, int tid)
{
    const int r = tid >> 1;
    const int s0 = (tid & 1) * 4;
    const uint32_t rb = (uint32_t)r * 128;
    const uint32_t rx = (uint32_t)(r & 7);
    const uint16_t* sAh = hH + (size_t)(m0 + r) * NHID + k0;
    const uint16_t* sAl = hL + (size_t)(m0 + r) * NHID + k0;
    const uint16_t* sBh = g_Wh + (size_t)(n0 + r) * NHID + k0;
    const uint16_t* sBl = g_Wl + (size_t)(n0 + r) * NHID + k0;
#pragma unroll
    for (int u = 0; u < 4; u++) {
        uint32_t s = (uint32_t)(s0 + u);
        uint32_t d = dstbase + rb + ((s ^ rx) << 4);
        CP16(d,               sAh + s * 8);
        CP16(d + TILE16K,     sAl + s * 8);
        CP16(d + 2 * TILE16K, sBh + s * 8);
        CP16(d + 3 * TILE16K, sBl + s * 8);
    }
}

// ---------------------------------------------------------------------------
// persistent kernel
// ---------------------------------------------------------------------------
__global__ __launch_bounds__(256, 1) void k_persist(
    const int* __restrict__ x,
    const float* __restrict__ Who, const float* __restrict__ bho,
    const float* __restrict__ gamma, const float* __restrict__ beta,
    float* __restrict__ out)
{
    extern __shared__ char smem[];
    const uint32_t sb = smem_to_u32(smem);
    const int tid = threadIdx.x;
    const int wid = tid >> 5;
    const int lane = tid & 31;
    const int b = blockIdx.x;
    const int n0 = (b & 7) * 128;
    const int m0 = (b >> 3) * 128;
    const int mw = wid >> 1;        // 0..3
    const int nw = wid & 1;         // 0..1

    int* xs = (int*)(smem + OFF_XS);
    float* hsB = (float*)(smem + OFF_HS);
    float* wsB = (float*)(smem + OFF_WS);
    const uint32_t buf0 = sb + OFF_BUF;

    // ldmatrix per-lane constants
    const int hl = lane >> 4;                       // 0/1: k8 half
    const uint32_t raA0 = (uint32_t)(mw * 32 + (lane & 15)) * 128;
    const uint32_t raA1 = raA0 + 16 * 128;
    const uint32_t rxA = (uint32_t)((mw * 32 + (lane & 15)) & 7);
    uint32_t rbB[4], rxB;
    {
        int r = nw * 64 + (lane & 15);
        rxB = (uint32_t)(r & 7);
#pragma unroll
        for (int g = 0; g < 4; g++) rbB[g] = (uint32_t)(r + g * 16) * 128;
    }

    unsigned epoch = 0;

    for (int t = 0; t < NT; t++) {
        const int cur = t & 1;
        const uint16_t* hHp = g_hA[cur];
        const uint16_t* hLp = g_hB[cur];
        uint16_t* hHn = g_hA[cur ^ 1];
        uint16_t* hLn = g_hB[cur ^ 1];

        if (tid < 128) xs[tid] = x[(m0 + tid) * NT + t];

        // ============ phase 1: h @ W^T via split-bf16 mma.sync ============
        float acc[2][8][4];
#pragma unroll
        for (int mt = 0; mt < 2; mt++)
#pragma unroll
            for (int j = 0; j < 8; j++)
#pragma unroll
                for (int q = 0; q < 4; q++) acc[mt][j][q] = 0.f;

        stage_chunk(buf0, hHp, hLp, m0, n0, 0, tid);
        CP_COMMIT();

        for (int c = 0; c < NCHUNK; c++) {
            const int p = c & 1;
            if (c < NCHUNK - 1) {
                stage_chunk(buf0 + (p ^ 1) * BUFSZ, hHp, hLp, m0, n0,
                            (c + 1) * KCH, tid);
                CP_COMMIT();
                CP_WAIT(1);
            } else {
                CP_WAIT(0);
            }
            __syncthreads();

            const uint32_t aB = buf0 + p * BUFSZ;
#pragma unroll
            for (int kt = 0; kt < 4; kt++) {
                const uint32_t segA = (uint32_t)(kt * 2 + hl);
                uint32_t ah0[4], ah1[4], al0[4], al1[4];
                {
                    uint32_t sa0 = aB + raA0 + ((segA ^ rxA) << 4);
                    uint32_t sa1 = aB + raA1 + ((segA ^ rxA) << 4);
                    ldsm4(ah0, sa0); ldsm4(ah1, sa1);
                    ldsm4(al0, sa0 + TILE16K); ldsm4(al1, sa1 + TILE16K);
                }
                uint32_t bh[4][4], bl[4][4];
#pragma unroll
                for (int g = 0; g < 4; g++) {
                    uint32_t sbp = aB + 2 * TILE16K + rbB[g] + ((segA ^ rxB) << 4);
                    ldsm4(bh[g], sbp);
                    ldsm4(bl[g], sbp + TILE16K);
                }
#pragma unroll
                for (int j = 0; j < 8; j++) {
                    const int g = j >> 1, o = j & 1;
                    mma16816(acc[0][j], ah0, bh[g][o], bh[g][2 + o]);
                    mma16816(acc[0][j], ah0, bl[g][o], bl[g][2 + o]);
                    mma16816(acc[0][j], al0, bh[g][o], bh[g][2 + o]);
                    mma16816(acc[1][j], ah1, bh[g][o], bh[g][2 + o]);
                    mma16816(acc[1][j], ah1, bl[g][o], bl[g][2 + o]);
                    mma16816(acc[1][j], al1, bh[g][o], bh[g][2 + o]);
                }
            }
            __syncthreads();
        }

        // ============ epilogue: +embW[x], relu, split-store h, stats ========
        {
            const int cb = n0 + nw * 64 + (lane & 3) * 2;
            float csum[8][2], csq[8][2];
#pragma unroll
            for (int j = 0; j < 8; j++) {
                csum[j][0] = 0.f; csum[j][1] = 0.f;
                csq[j][0] = 0.f;  csq[j][1] = 0.f;
            }
#pragma unroll
            for (int mt = 0; mt < 2; mt++) {
#pragma unroll
                for (int rr = 0; rr < 2; rr++) {
                    const int lrow = mw * 32 + mt * 16 + rr * 8 + (lane >> 2);
                    const int row = m0 + lrow;
                    const float* ew = g_embW + (size_t)xs[lrow] * NHID;
                    uint16_t* dH = hHn + (size_t)row * NHID;
                    uint16_t* dL = hLn + (size_t)row * NHID;
#pragma unroll
                    for (int j = 0; j < 8; j++) {
                        const int col = cb + j * 8;
                        float2 e = *(const float2*)(ew + col);
                        float v0 = fmaxf(acc[mt][j][rr * 2 + 0] + e.x, 0.f);
                        float v1 = fmaxf(acc[mt][j][rr * 2 + 1] + e.y, 0.f);
                        uint32_t hw, lw;
                        asm("cvt.rn.bf16x2.f32 %0, %1, %2;"
                            : "=r"(hw) : "f"(v1), "f"(v0));
                        float r0 = v0 - __uint_as_float(hw << 16);
                        float r1 = v1 - __uint_as_float(hw & 0xffff0000u);
                        asm("cvt.rn.bf16x2.f32 %0, %1, %2;"
                            : "=r"(lw) : "f"(r1), "f"(r0));
                        *(uint32_t*)(dH + col) = hw;
                        *(uint32_t*)(dL + col) = lw;
                        csum[j][0] += v0; csum[j][1] += v1;
                        csq[j][0] = fmaf(v0, v0, csq[j][0]);
                        csq[j][1] = fmaf(v1, v1, csq[j][1]);
                    }
                }
            }
#pragma unroll
            for (int j = 0; j < 8; j++) {
                float s0 = csum[j][0], s1 = csum[j][1];
                float q0 = csq[j][0], q1 = csq[j][1];
                s0 += __shfl_down_sync(~0u, s0, 16);
                s1 += __shfl_down_sync(~0u, s1, 16);
                q0 += __shfl_down_sync(~0u, q0, 16);
                q1 += __shfl_down_sync(~0u, q1, 16);
                s0 += __shfl_down_sync(~0u, s0, 8);
                s1 += __shfl_down_sync(~0u, s1, 8);
                q0 += __shfl_down_sync(~0u, q0, 8);
                q1 += __shfl_down_sync(~0u, q1, 8);
                s0 += __shfl_down_sync(~0u, s0, 4);
                s1 += __shfl_down_sync(~0u, s1, 4);
                q0 += __shfl_down_sync(~0u, q0, 4);
                q1 += __shfl_down_sync(~0u, q1, 4);
                if (lane < 4) {
                    const int col = n0 + nw * 64 + j * 8 + lane * 2;
                    atomicAdd(&g_sum[col], s0);
                    atomicAdd(&g_sum[col + 1], s1);
                    atomicAdd(&g_sumsq[col], q0);
                    atomicAdd(&g_sumsq[col + 1], q1);
                }
            }
        }

        gridbar(epoch);

        // ============ phase 2: BN finalize (blocks 0..3) ============
        if (b < 4) {
            int k = b * 256 + tid;
            float mu = g_sum[k] * (1.f / NB);
            float var = g_sumsq[k] * (1.f / NB) - mu * mu;
            float rs = rsqrtf(var + EPS);
            float sc = rs * gamma[k];
            g_scale[k] = sc;
            g_shift[k] = beta[k] - mu * sc;
            g_sum[k] = 0.f;
            g_sumsq[k] = 0.f;
        }

        gridbar(epoch);

        // ============ phase 3: output GEMM (16 rows/block) ============
        {
            const uint16_t* hH = hHn;
            const uint16_t* hL = hLn;
            const int om0 = b * 16;
            const int v31 = tid & 31;
            const int rg = tid >> 5;
            float oacc[2] = {0.f, 0.f};

            for (int k0 = 0; k0 < NHID; k0 += 64) {
                {
                    int rr = tid >> 4;
                    int qd = (tid & 15) * 4;
                    const uint16_t* ph = hH + (size_t)(om0 + rr) * NHID + k0 + qd;
                    const uint16_t* pl = hL + (size_t)(om0 + rr) * NHID + k0 + qd;
                    uint2 uh = *(const uint2*)ph;
                    uint2 ul = *(const uint2*)pl;
                    float2 fh0 = __bfloat1622float2(*(__nv_bfloat162*)&uh.x);
                    float2 fh1 = __bfloat1622float2(*(__nv_bfloat162*)&uh.y);
                    float2 fl0 = __bfloat1622float2(*(__nv_bfloat162*)&ul.x);
                    float2 fl1 = __bfloat1622float2(*(__nv_bfloat162*)&ul.y);
                    float4 sv = *(const float4*)&g_scale[k0 + qd];
                    float4 fv = *(const float4*)&g_shift[k0 + qd];
                    hsB[rr * 64 + qd + 0] = fmaf(fh0.x + fl0.x, sv.x, fv.x);
                    hsB[rr * 64 + qd + 1] = fmaf(fh0.y + fl0.y, sv.y, fv.y);
                    hsB[rr * 64 + qd + 2] = fmaf(fh1.x + fl1.x, sv.z, fv.z);
                    hsB[rr * 64 + qd + 3] = fmaf(fh1.y + fl1.y, sv.w, fv.w);
                }
                for (int idx = tid; idx < 64 * 32; idx += 256) {
                    int kk = idx & 63;
                    int vv = idx >> 6;
                    wsB[kk * 33 + vv] = (vv < NVOC) ? Who[vv * NHID + k0 + kk] : 0.f;
                }
                __syncthreads();
#pragma unroll
                for (int kk = 0; kk < 64; kk += 4) {
                    float w0 = wsB[(kk + 0) * 33 + v31];
                    float w1 = wsB[(kk + 1) * 33 + v31];
                    float w2 = wsB[(kk + 2) * 33 + v31];
                    float w3 = wsB[(kk + 3) * 33 + v31];
#pragma unroll
                    for (int r = 0; r < 2; r++) {
                        float4 hv = *(const float4*)&hsB[(rg * 2 + r) * 64 + kk];
                        float s = fmaf(hv.x, w0, oacc[r]);
                        s = fmaf(hv.y, w1, s);
                        s = fmaf(hv.z, w2, s);
                        oacc[r] = fmaf(hv.w, w3, s);
                    }
                }
                __syncthreads();
            }

            if (v31 < NVOC) {
                float bv = bho[v31];
#pragma unroll
                for (int r = 0; r < 2; r++) {
                    size_t orow = om0 + rg * 2 + r;
                    out[orow * (size_t)(NT * NVOC) + (size_t)t * NVOC + v31] =
                        oacc[r] + bv;
                }
            }
        }
    }
}

// ---------------------------------------------------------------------------
extern "C" void kernel_launch(void* const* d_in, const int* in_sizes, int n_in,
                              void* d_out, int out_size)
{
    const int*   x     = (const int*)d_in[0];
    const float* emb   = (const float*)d_in[1];
    const float* Whh   = (const float*)d_in[2];
    const float* bhh   = (const float*)d_in[3];
    const float* Who   = (const float*)d_in[4];
    const float* bho   = (const float*)d_in[5];
    const float* gamma = (const float*)d_in[6];
    const float* beta  = (const float*)d_in[7];
    float* out = (float*)d_out;

    cudaFuncSetAttribute(k_persist, cudaFuncAttributeMaxDynamicSharedMemorySize,
                         SMEM_TOTAL);

    k_init<<<1024, 256>>>(Whh, emb, bhh);
    k_persist<<<NBLK, 256, SMEM_TOTAL>>>(x, Who, bho, gamma, beta, out);
}

// round 7
// speedup vs baseline: 2.0954x; 1.0224x over previous
#include <cuda_runtime.h>
#include <cuda_bf16.h>
#include <cstdint>

#define NB   2048
#define NT   512
#define NHID 1024
#define NVOC 31
#define EPS  1e-5f
#define NBLK 128
#define NTHR 512

#define KCH     64
#define NCHUNK  (NHID / KCH)        // 16
#define TILE16K 16384               // one 128x64 bf16 tile, 128B rows
#define BUFSZ   (4 * TILE16K)

// smem layout (dynamic)
#define OFF_XS   0                  // 128 ints   -> 512
#define OFF_SS   512                // scale 1024f -> 4608
#define OFF_SH   4608               // shift 1024f -> 8704
#define OFF_GA   8704               // gamma      -> 12800
#define OFF_BE   12800              // beta       -> 16896
#define OFF_HS   16896              // 16x64 f    -> 20992
#define OFF_WS   20992              // 64x33 f    -> 29440
#define OFF_BUF  29440              // 128B aligned
#define SMEM_TOTAL (OFF_BUF + 2 * BUFSZ)   // 160512

// ---- persistent device state ----
__device__ __align__(16) uint16_t g_hA[2][NB * NHID];   // h bf16 hi
__device__ __align__(16) uint16_t g_hB[2][NB * NHID];   // h bf16 lo
__device__ __align__(16) uint16_t g_Wh[NHID * NHID];    // W_hh bf16 hi
__device__ __align__(16) uint16_t g_Wl[NHID * NHID];    // W_hh bf16 lo
__device__ __align__(16) float    g_embW[NVOC * NHID];  // emb @ W^T + b_hh
__device__ __align__(16) float    g_sum3[3][NHID];
__device__ __align__(16) float    g_sumsq3[3][NHID];
__device__ unsigned g_count;

// ============================ PTX helpers ============================
__device__ __forceinline__ uint32_t smem_to_u32(const void* p) {
    uint32_t a;
    asm("{ .reg .u64 t; cvta.to.shared.u64 t, %1; cvt.u32.u64 %0, t; }"
        : "=r"(a) : "l"(p));
    return a;
}
#define CP16(dst, src) \
    asm volatile("cp.async.cg.shared.global [%0], [%1], 16;" \
                 :: "r"(dst), "l"(src) : "memory")
#define CP_COMMIT() asm volatile("cp.async.commit_group;" ::: "memory")
#define CP_WAIT(n)  asm volatile("cp.async.wait_group %0;" :: "n"(n) : "memory")

__device__ __forceinline__ void ldsm4(uint32_t* r, uint32_t addr) {
    asm volatile("ldmatrix.sync.aligned.m8n8.x4.shared.b16 {%0,%1,%2,%3}, [%4];"
                 : "=r"(r[0]), "=r"(r[1]), "=r"(r[2]), "=r"(r[3]) : "r"(addr));
}
__device__ __forceinline__ void mma16816(float* c, const uint32_t* a,
                                         uint32_t b0, uint32_t b1) {
    asm volatile(
        "mma.sync.aligned.m16n8k16.row.col.f32.bf16.bf16.f32 "
        "{%0,%1,%2,%3}, {%4,%5,%6,%7}, {%8,%9}, {%0,%1,%2,%3};"
        : "+f"(c[0]), "+f"(c[1]), "+f"(c[2]), "+f"(c[3])
        : "r"(a[0]), "r"(a[1]), "r"(a[2]), "r"(a[3]), "r"(b0), "r"(b1));
}

// ---------------------------------------------------------------------------
// init
// ---------------------------------------------------------------------------
__global__ void k_init(const float* __restrict__ W, const float* __restrict__ emb,
                       const float* __restrict__ bhh) {
    int gid = blockIdx.x * blockDim.x + threadIdx.x;
    int stride = gridDim.x * blockDim.x;
    uint32_t* zA = (uint32_t*)g_hA[0];
    uint32_t* zB = (uint32_t*)g_hB[0];
    for (int i = gid; i < NB * NHID / 2; i += stride) { zA[i] = 0u; zB[i] = 0u; }
    for (int i = gid; i < NHID * NHID; i += stride) {
        float v = W[i];
        __nv_bfloat16 h = __float2bfloat16(v);
        g_Wh[i] = __bfloat16_as_ushort(h);
        g_Wl[i] = __bfloat16_as_ushort(__float2bfloat16(v - __bfloat162float(h)));
    }
    if (gid < NVOC * NHID) {
        int v = gid >> 10, n = gid & (NHID - 1);
        const float4* er = (const float4*)(emb + (size_t)v * NHID);
        const float4* wr = (const float4*)(W + (size_t)n * NHID);
        float s0 = 0.f, s1 = 0.f, s2 = 0.f, s3 = 0.f;
        for (int k = 0; k < NHID / 4; k++) {
            float4 e = er[k], w = wr[k];
            s0 = fmaf(e.x, w.x, s0); s1 = fmaf(e.y, w.y, s1);
            s2 = fmaf(e.z, w.z, s2); s3 = fmaf(e.w, w.w, s3);
        }
        g_embW[gid] = (s0 + s1) + (s2 + s3) + bhh[n];
    }
    if (gid < NHID) {
        for (int r = 0; r < 3; r++) { g_sum3[r][gid] = 0.f; g_sumsq3[r][gid] = 0.f; }
    }
    if (gid == 0) g_count = 0u;
}

// ---------------------------------------------------------------------------
// grid barrier (all 128 blocks resident)
// ---------------------------------------------------------------------------
__device__ __forceinline__ void gridbar(unsigned& epoch) {
    __syncthreads();
    epoch += NBLK;
    if (threadIdx.x == 0) {
        __threadfence();
        atomicAdd(&g_count, 1u);
        while (*(volatile unsigned*)&g_count < epoch) { }
        __threadfence();
    }
    __syncthreads();
}

// stage one 64-K chunk: A(hi,lo), B(hi,lo), SW128-swizzled, 512 threads
__device__ __forceinline__ void stage_chunk(
    uint32_t dstbase, const uint16_t* __restrict__ hH,
    const uint16_t* __restrict__ hL, int m0, int n0, int k0, int tid)
{
    const int r = tid >> 2;                 // 0..127
    const int s0 = (tid & 3) * 2;
    const uint32_t rb = (uint32_t)r * 128;
    const uint32_t rx = (uint32_t)(r & 7);
    const uint16_t* sAh = hH + (size_t)(m0 + r) * NHID + k0;
    const uint16_t* sAl = hL + (size_t)(m0 + r) * NHID + k0;
    const uint16_t* sBh = g_Wh + (size_t)(n0 + r) * NHID + k0;
    const uint16_t* sBl = g_Wl + (size_t)(n0 + r) * NHID + k0;
#pragma unroll
    for (int u = 0; u < 2; u++) {
        uint32_t s = (uint32_t)(s0 + u);
        uint32_t d = dstbase + rb + ((s ^ rx) << 4);
        CP16(d,               sAh + s * 8);
        CP16(d + TILE16K,     sAl + s * 8);
        CP16(d + 2 * TILE16K, sBh + s * 8);
        CP16(d + 3 * TILE16K, sBl + s * 8);
    }
}

// ---------------------------------------------------------------------------
// persistent kernel: 512 threads, 16 warps, warp tile 32x32
// ---------------------------------------------------------------------------
__global__ __launch_bounds__(NTHR, 1) void k_persist(
    const int* __restrict__ x,
    const float* __restrict__ Who, const float* __restrict__ bho,
    const float* __restrict__ gamma, const float* __restrict__ beta,
    float* __restrict__ out)
{
    extern __shared__ char smem[];
    const uint32_t sb = smem_to_u32(smem);
    const int tid = threadIdx.x;
    const int wid = tid >> 5;
    const int lane = tid & 31;
    const int b = blockIdx.x;
    const int n0 = (b & 7) * 128;
    const int m0 = (b >> 3) * 128;
    const int mw = wid >> 2;        // 0..3 : 32-row slice
    const int nw = wid & 3;         // 0..3 : 32-col slice

    int* xs = (int*)(smem + OFF_XS);
    float* sS = (float*)(smem + OFF_SS);
    float* sH = (float*)(smem + OFF_SH);
    float* sGa = (float*)(smem + OFF_GA);
    float* sBe = (float*)(smem + OFF_BE);
    float* hsB = (float*)(smem + OFF_HS);
    float* wsB = (float*)(smem + OFF_WS);
    const uint32_t buf0 = sb + OFF_BUF;

    // ldmatrix per-lane constants
    const uint32_t raA0 = (uint32_t)(mw * 32 + (lane & 15)) * 128;
    const uint32_t raA1 = raA0 + 16 * 128;
    const uint32_t rxA = (uint32_t)(lane & 7);
    const uint32_t rbB0 = (uint32_t)(nw * 32 + (lane & 15)) * 128;
    const uint32_t rbB1 = rbB0 + 16 * 128;
    const uint32_t rxB = rxA;
    const int hl = lane >> 4;

    // preload gamma/beta; xs(0)
    sGa[tid] = gamma[tid]; sGa[tid + 512] = gamma[tid + 512];
    sBe[tid] = beta[tid];  sBe[tid + 512] = beta[tid + 512];
    if (tid < 128) xs[tid] = x[(m0 + tid) * NT + 0];
    __syncthreads();

    stage_chunk(buf0, g_hA[0], g_hB[0], m0, n0, 0, tid);
    CP_COMMIT();

    unsigned epoch = 0;

    for (int t = 0; t < NT; t++) {
        const int cur = t & 1;
        const uint16_t* hHp = g_hA[cur];
        const uint16_t* hLp = g_hB[cur];
        uint16_t* hHn = g_hA[cur ^ 1];
        uint16_t* hLn = g_hB[cur ^ 1];
        const int sp = t % 3;

        // ============ phase 1: h @ W^T via split-bf16 mma.sync ============
        float acc[2][4][4];
#pragma unroll
        for (int mt = 0; mt < 2; mt++)
#pragma unroll
            for (int j = 0; j < 4; j++)
#pragma unroll
                for (int q = 0; q < 4; q++) acc[mt][j][q] = 0.f;

        for (int c = 0; c < NCHUNK; c++) {
            const int p = c & 1;
            if (c < NCHUNK - 1) {
                stage_chunk(buf0 + (p ^ 1) * BUFSZ, hHp, hLp, m0, n0,
                            (c + 1) * KCH, tid);
                CP_COMMIT();
                CP_WAIT(1);
            } else {
                CP_WAIT(0);
            }
            __syncthreads();

            const uint32_t aB = buf0 + p * BUFSZ;
#pragma unroll
            for (int kt = 0; kt < 4; kt++) {
                const uint32_t segA = (uint32_t)(kt * 2 + hl);
                uint32_t ah0[4], ah1[4], al0[4], al1[4];
                {
                    uint32_t sa0 = aB + raA0 + ((segA ^ rxA) << 4);
                    uint32_t sa1 = aB + raA1 + ((segA ^ rxA) << 4);
                    ldsm4(ah0, sa0); ldsm4(ah1, sa1);
                    ldsm4(al0, sa0 + TILE16K); ldsm4(al1, sa1 + TILE16K);
                }
                uint32_t bh[2][4], bl[2][4];
                {
                    uint32_t sb0 = aB + 2 * TILE16K + rbB0 + ((segA ^ rxB) << 4);
                    uint32_t sb1 = aB + 2 * TILE16K + rbB1 + ((segA ^ rxB) << 4);
                    ldsm4(bh[0], sb0); ldsm4(bh[1], sb1);
                    ldsm4(bl[0], sb0 + TILE16K); ldsm4(bl[1], sb1 + TILE16K);
                }
#pragma unroll
                for (int j = 0; j < 4; j++) {
                    const int g = j >> 1, o = j & 1;
                    mma16816(acc[0][j], ah0, bh[g][o], bh[g][2 + o]);
                    mma16816(acc[0][j], ah0, bl[g][o], bl[g][2 + o]);
                    mma16816(acc[0][j], al0, bh[g][o], bh[g][2 + o]);
                    mma16816(acc[1][j], ah1, bh[g][o], bh[g][2 + o]);
                    mma16816(acc[1][j], ah1, bl[g][o], bl[g][2 + o]);
                    mma16816(acc[1][j], al1, bh[g][o], bh[g][2 + o]);
                }
            }
            __syncthreads();
        }

        // ============ epilogue: +embW[x], relu, split-store h, stats ========
        {
            const int cb = n0 + nw * 32 + (lane & 3) * 2;
            float csum[4][2], csq[4][2];
#pragma unroll
            for (int j = 0; j < 4; j++) {
                csum[j][0] = 0.f; csum[j][1] = 0.f;
                csq[j][0] = 0.f;  csq[j][1] = 0.f;
            }
#pragma unroll
            for (int mt = 0; mt < 2; mt++) {
#pragma unroll
                for (int rr = 0; rr < 2; rr++) {
                    const int lrow = mw * 32 + mt * 16 + rr * 8 + (lane >> 2);
                    const int row = m0 + lrow;
                    const float* ew = g_embW + (size_t)xs[lrow] * NHID;
                    uint16_t* dH = hHn + (size_t)row * NHID;
                    uint16_t* dL = hLn + (size_t)row * NHID;
#pragma unroll
                    for (int j = 0; j < 4; j++) {
                        const int col = cb + j * 8;
                        float2 e = *(const float2*)(ew + col);
                        float v0 = fmaxf(acc[mt][j][rr * 2 + 0] + e.x, 0.f);
                        float v1 = fmaxf(acc[mt][j][rr * 2 + 1] + e.y, 0.f);
                        uint32_t hw, lw;
                        asm("cvt.rn.bf16x2.f32 %0, %1, %2;"
                            : "=r"(hw) : "f"(v1), "f"(v0));
                        float r0 = v0 - __uint_as_float(hw << 16);
                        float r1 = v1 - __uint_as_float(hw & 0xffff0000u);
                        asm("cvt.rn.bf16x2.f32 %0, %1, %2;"
                            : "=r"(lw) : "f"(r1), "f"(r0));
                        *(uint32_t*)(dH + col) = hw;
                        *(uint32_t*)(dL + col) = lw;
                        csum[j][0] += v0; csum[j][1] += v1;
                        csq[j][0] = fmaf(v0, v0, csq[j][0]);
                        csq[j][1] = fmaf(v1, v1, csq[j][1]);
                    }
                }
            }
#pragma unroll
            for (int j = 0; j < 4; j++) {
                float s0 = csum[j][0], s1 = csum[j][1];
                float q0 = csq[j][0], q1 = csq[j][1];
                s0 += __shfl_down_sync(~0u, s0, 16);
                s1 += __shfl_down_sync(~0u, s1, 16);
                q0 += __shfl_down_sync(~0u, q0, 16);
                q1 += __shfl_down_sync(~0u, q1, 16);
                s0 += __shfl_down_sync(~0u, s0, 8);
                s1 += __shfl_down_sync(~0u, s1, 8);
                q0 += __shfl_down_sync(~0u, q0, 8);
                q1 += __shfl_down_sync(~0u, q1, 8);
                s0 += __shfl_down_sync(~0u, s0, 4);
                s1 += __shfl_down_sync(~0u, s1, 4);
                q0 += __shfl_down_sync(~0u, q0, 4);
                q1 += __shfl_down_sync(~0u, q1, 4);
                if (lane < 4) {
                    const int col = n0 + nw * 32 + j * 8 + lane * 2;
                    atomicAdd(&g_sum3[sp][col], s0);
                    atomicAdd(&g_sum3[sp][col + 1], s1);
                    atomicAdd(&g_sumsq3[sp][col], q0);
                    atomicAdd(&g_sumsq3[sp][col + 1], q1);
                }
            }
        }

        gridbar(epoch);

        // ======== post-bar: zero stale stats; scale/shift; xs(t+1) =========
        {
            const int st = (t + 2) % 3;   // == (t-1) mod 3
            if (tid < 8) g_sum3[st][b * 8 + tid] = 0.f;
            else if (tid < 16) g_sumsq3[st][b * 8 + tid - 8] = 0.f;
#pragma unroll
            for (int u = 0; u < 2; u++) {
                const int c = tid + u * NTHR;
                float mu = g_sum3[sp][c] * (1.f / NB);
                float var = g_sumsq3[sp][c] * (1.f / NB) - mu * mu;
                float rs = rsqrtf(var + EPS);
                float sc = rs * sGa[c];
                sS[c] = sc;
                sH[c] = sBe[c] - mu * sc;
            }
            if (t < NT - 1 && tid < 128) xs[tid] = x[(m0 + tid) * NT + t + 1];
        }
        __syncthreads();

        // prefetch chunk 0 of step t+1 (hidden under phase 3)
        if (t < NT - 1) {
            stage_chunk(buf0, hHn, hLn, m0, n0, 0, tid);
            CP_COMMIT();
        }

        // ============ phase 3: output GEMM (16 rows/block) ============
        {
            const int om0 = b * 16;
            const int v31 = lane;
            const int rg = wid;           // 0..15: one row per warp
            float oa0 = 0.f, oa1 = 0.f, oa2 = 0.f, oa3 = 0.f;

            for (int k0 = 0; k0 < NHID; k0 += 64) {
                {
                    const int i0 = tid * 2;
                    const int rr = i0 >> 6, kk = i0 & 63;
                    const uint16_t* ph = hHn + (size_t)(om0 + rr) * NHID + k0 + kk;
                    const uint16_t* pl = hLn + (size_t)(om0 + rr) * NHID + k0 + kk;
                    uint32_t uh = *(const uint32_t*)ph;
                    uint32_t ul = *(const uint32_t*)pl;
                    float2 fh = __bfloat1622float2(*(__nv_bfloat162*)&uh);
                    float2 fl = __bfloat1622float2(*(__nv_bfloat162*)&ul);
                    hsB[rr * 64 + kk]     = fmaf(fh.x + fl.x, sS[k0 + kk],     sH[k0 + kk]);
                    hsB[rr * 64 + kk + 1] = fmaf(fh.y + fl.y, sS[k0 + kk + 1], sH[k0 + kk + 1]);
                }
                for (int idx = tid; idx < 64 * 32; idx += NTHR) {
                    int kk = idx & 63;
                    int vv = idx >> 6;
                    wsB[kk * 33 + vv] = (vv < NVOC) ? Who[vv * NHID + k0 + kk] : 0.f;
                }
                __syncthreads();
                const float* hrow = hsB + rg * 64;
#pragma unroll
                for (int kk = 0; kk < 64; kk += 4) {
                    float4 h4 = *(const float4*)(hrow + kk);
                    oa0 = fmaf(h4.x, wsB[(kk + 0) * 33 + v31], oa0);
                    oa1 = fmaf(h4.y, wsB[(kk + 1) * 33 + v31], oa1);
                    oa2 = fmaf(h4.z, wsB[(kk + 2) * 33 + v31], oa2);
                    oa3 = fmaf(h4.w, wsB[(kk + 3) * 33 + v31], oa3);
                }
                __syncthreads();
            }

            if (v31 < NVOC) {
                size_t orow = om0 + rg;
                out[orow * (size_t)(NT * NVOC) + (size_t)t * NVOC + v31] =
                    (oa0 + oa1) + (oa2 + oa3) + bho[v31];
            }
        }
    }
}

// ---------------------------------------------------------------------------
extern "C" void kernel_launch(void* const* d_in, const int* in_sizes, int n_in,
                              void* d_out, int out_size)
{
    const int*   x     = (const int*)d_in[0];
    const float* emb   = (const float*)d_in[1];
    const float* Whh   = (const float*)d_in[2];
    const float* bhh   = (const float*)d_in[3];
    const float* Who   = (const float*)d_in[4];
    const float* bho   = (const float*)d_in[5];
    const float* gamma = (const float*)d_in[6];
    const float* beta  = (const float*)d_in[7];
    float* out = (float*)d_out;

    cudaFuncSetAttribute(k_persist, cudaFuncAttributeMaxDynamicSharedMemorySize,
                         SMEM_TOTAL);

    k_init<<<1024, 256>>>(Whh, emb, bhh);
    k_persist<<<NBLK, NTHR, SMEM_TOTAL>>>(x, Who, bho, gamma, beta, out);
}

// round 8
// speedup vs baseline: 2.5736x; 1.2282x over previous
#include <cuda_runtime.h>
#include <cuda_fp16.h>
#include <cstdint>

#define NB   2048
#define NT   512
#define NHID 1024
#define NVOC 31
#define EPS  1e-5f
#define NBLK 128
#define NTHR 512

#define KCH     64
#define NCHUNK  (NHID / KCH)        // 16
#define TILE16K 16384               // one 128x64 fp16 tile, 128B rows
#define BUFSZ   (3 * TILE16K)       // A, Bh, Bl

// smem layout (dynamic)
#define OFF_XS   0                  // 128 ints   -> 512
#define OFF_SS   512                // scale 1024f -> 4608
#define OFF_SH   4608               // shift 1024f -> 8704
#define OFF_GA   8704               // gamma      -> 12800
#define OFF_BE   12800              // beta       -> 16896
#define OFF_HS   16896              // 16x64 f    -> 20992
#define OFF_WS   20992              // 64x33 f    -> 29440
#define OFF_BUF  29440              // 128B aligned
#define SMEM_TOTAL (OFF_BUF + 2 * BUFSZ)   // 127744

// ---- persistent device state ----
__device__ __align__(16) uint16_t g_h16[2][NB * NHID];  // h fp16
__device__ __align__(16) uint16_t g_Wh[NHID * NHID];    // W_hh fp16 hi
__device__ __align__(16) uint16_t g_Wl[NHID * NHID];    // W_hh fp16 lo
__device__ __align__(16) float    g_embW[NVOC * NHID];  // emb @ W^T + b_hh
__device__ __align__(16) float    g_sum3[3][NHID];
__device__ __align__(16) float    g_sumsq3[3][NHID];
__device__ unsigned g_count;

// ============================ PTX helpers ============================
__device__ __forceinline__ uint32_t smem_to_u32(const void* p) {
    uint32_t a;
    asm("{ .reg .u64 t; cvta.to.shared.u64 t, %1; cvt.u32.u64 %0, t; }"
        : "=r"(a) : "l"(p));
    return a;
}
#define CP16(dst, src) \
    asm volatile("cp.async.cg.shared.global [%0], [%1], 16;" \
                 :: "r"(dst), "l"(src) : "memory")
#define CP_COMMIT() asm volatile("cp.async.commit_group;" ::: "memory")
#define CP_WAIT(n)  asm volatile("cp.async.wait_group %0;" :: "n"(n) : "memory")

__device__ __forceinline__ void ldsm4(uint32_t* r, uint32_t addr) {
    asm volatile("ldmatrix.sync.aligned.m8n8.x4.shared.b16 {%0,%1,%2,%3}, [%4];"
                 : "=r"(r[0]), "=r"(r[1]), "=r"(r[2]), "=r"(r[3]) : "r"(addr));
}
__device__ __forceinline__ void mma16816(float* c, const uint32_t* a,
                                         uint32_t b0, uint32_t b1) {
    asm volatile(
        "mma.sync.aligned.m16n8k16.row.col.f32.f16.f16.f32 "
        "{%0,%1,%2,%3}, {%4,%5,%6,%7}, {%8,%9}, {%0,%1,%2,%3};"
        : "+f"(c[0]), "+f"(c[1]), "+f"(c[2]), "+f"(c[3])
        : "r"(a[0]), "r"(a[1]), "r"(a[2]), "r"(a[3]), "r"(b0), "r"(b1));
}

// ---------------------------------------------------------------------------
// init: zero h[0]; split W_hh into fp16 hi/lo; embW = emb@W^T + b_hh
// ---------------------------------------------------------------------------
__global__ void k_init(const float* __restrict__ W, const float* __restrict__ emb,
                       const float* __restrict__ bhh) {
    int gid = blockIdx.x * blockDim.x + threadIdx.x;
    int stride = gridDim.x * blockDim.x;
    uint32_t* zA = (uint32_t*)g_h16[0];
    for (int i = gid; i < NB * NHID / 2; i += stride) zA[i] = 0u;
    for (int i = gid; i < NHID * NHID; i += stride) {
        float v = W[i];
        __half h = __float2half_rn(v);
        g_Wh[i] = __half_as_ushort(h);
        g_Wl[i] = __half_as_ushort(__float2half_rn(v - __half2float(h)));
    }
    if (gid < NVOC * NHID) {
        int v = gid >> 10, n = gid & (NHID - 1);
        const float4* er = (const float4*)(emb + (size_t)v * NHID);
        const float4* wr = (const float4*)(W + (size_t)n * NHID);
        float s0 = 0.f, s1 = 0.f, s2 = 0.f, s3 = 0.f;
        for (int k = 0; k < NHID / 4; k++) {
            float4 e = er[k], w = wr[k];
            s0 = fmaf(e.x, w.x, s0); s1 = fmaf(e.y, w.y, s1);
            s2 = fmaf(e.z, w.z, s2); s3 = fmaf(e.w, w.w, s3);
        }
        g_embW[gid] = (s0 + s1) + (s2 + s3) + bhh[n];
    }
    if (gid < NHID) {
        for (int r = 0; r < 3; r++) { g_sum3[r][gid] = 0.f; g_sumsq3[r][gid] = 0.f; }
    }
    if (gid == 0) g_count = 0u;
}

// ---------------------------------------------------------------------------
// grid barrier (all 128 blocks resident)
// ---------------------------------------------------------------------------
__device__ __forceinline__ void gridbar(unsigned& epoch) {
    __syncthreads();
    epoch += NBLK;
    if (threadIdx.x == 0) {
        __threadfence();
        atomicAdd(&g_count, 1u);
        while (*(volatile unsigned*)&g_count < epoch) { }
        __threadfence();
    }
    __syncthreads();
}

// stage one 64-K chunk: A (h fp16), Bh, Bl; SW128-swizzled; 512 threads
__device__ __forceinline__ void stage_chunk(
    uint32_t dstbase, const uint16_t* __restrict__ hsrc,
    int m0, int n0, int k0, int tid)
{
    const int r = tid >> 2;                 // 0..127
    const int s0 = (tid & 3) * 2;
    const uint32_t rb = (uint32_t)r * 128;
    const uint32_t rx = (uint32_t)(r & 7);
    const uint16_t* sA  = hsrc + (size_t)(m0 + r) * NHID + k0;
    const uint16_t* sBh = g_Wh + (size_t)(n0 + r) * NHID + k0;
    const uint16_t* sBl = g_Wl + (size_t)(n0 + r) * NHID + k0;
#pragma unroll
    for (int u = 0; u < 2; u++) {
        uint32_t s = (uint32_t)(s0 + u);
        uint32_t d = dstbase + rb + ((s ^ rx) << 4);
        CP16(d,               sA + s * 8);
        CP16(d + TILE16K,     sBh + s * 8);
        CP16(d + 2 * TILE16K, sBl + s * 8);
    }
}

// ---------------------------------------------------------------------------
// persistent kernel: 512 threads, 16 warps, warp tile 32x32
// ---------------------------------------------------------------------------
__global__ __launch_bounds__(NTHR, 1) void k_persist(
    const int* __restrict__ x,
    const float* __restrict__ Who, const float* __restrict__ bho,
    const float* __restrict__ gamma, const float* __restrict__ beta,
    float* __restrict__ out)
{
    extern __shared__ char smem[];
    const uint32_t sb = smem_to_u32(smem);
    const int tid = threadIdx.x;
    const int wid = tid >> 5;
    const int lane = tid & 31;
    const int b = blockIdx.x;
    const int n0 = (b & 7) * 128;
    const int m0 = (b >> 3) * 128;
    const int mw = wid >> 2;        // 0..3 : 32-row slice
    const int nw = wid & 3;         // 0..3 : 32-col slice

    int* xs = (int*)(smem + OFF_XS);
    float* sS = (float*)(smem + OFF_SS);
    float* sH = (float*)(smem + OFF_SH);
    float* sGa = (float*)(smem + OFF_GA);
    float* sBe = (float*)(smem + OFF_BE);
    float* hsB = (float*)(smem + OFF_HS);
    float* wsB = (float*)(smem + OFF_WS);
    const uint32_t buf0 = sb + OFF_BUF;

    // ldmatrix per-lane constants
    const uint32_t raA0 = (uint32_t)(mw * 32 + (lane & 15)) * 128;
    const uint32_t raA1 = raA0 + 16 * 128;
    const uint32_t rxA = (uint32_t)(lane & 7);
    const uint32_t rbB0 = (uint32_t)(nw * 32 + (lane & 15)) * 128;
    const uint32_t rbB1 = rbB0 + 16 * 128;
    const uint32_t rxB = rxA;
    const int hl = lane >> 4;

    sGa[tid] = gamma[tid]; sGa[tid + 512] = gamma[tid + 512];
    sBe[tid] = beta[tid];  sBe[tid + 512] = beta[tid + 512];
    if (tid < 128) xs[tid] = x[(m0 + tid) * NT + 0];
    __syncthreads();

    stage_chunk(buf0, g_h16[0], m0, n0, 0, tid);
    CP_COMMIT();

    unsigned epoch = 0;

    for (int t = 0; t < NT; t++) {
        const int cur = t & 1;
        const uint16_t* hp = g_h16[cur];
        uint16_t* hn = g_h16[cur ^ 1];
        const int sp = t % 3;

        // ============ phase 1: h @ W^T via fp16 2-product mma ============
        float acc[2][4][4];
#pragma unroll
        for (int mt = 0; mt < 2; mt++)
#pragma unroll
            for (int j = 0; j < 4; j++)
#pragma unroll
                for (int q = 0; q < 4; q++) acc[mt][j][q] = 0.f;

        for (int c = 0; c < NCHUNK; c++) {
            const int p = c & 1;
            if (c < NCHUNK - 1) {
                stage_chunk(buf0 + (p ^ 1) * BUFSZ, hp, m0, n0, (c + 1) * KCH, tid);
                CP_COMMIT();
                CP_WAIT(1);
            } else {
                CP_WAIT(0);
            }
            __syncthreads();

            const uint32_t aB = buf0 + p * BUFSZ;
#pragma unroll
            for (int kt = 0; kt < 4; kt++) {
                const uint32_t segA = (uint32_t)(kt * 2 + hl);
                uint32_t a0[4], a1[4];
                {
                    uint32_t sa0 = aB + raA0 + ((segA ^ rxA) << 4);
                    uint32_t sa1 = aB + raA1 + ((segA ^ rxA) << 4);
                    ldsm4(a0, sa0); ldsm4(a1, sa1);
                }
                uint32_t bh[2][4], bl[2][4];
                {
                    uint32_t sb0 = aB + TILE16K + rbB0 + ((segA ^ rxB) << 4);
                    uint32_t sb1 = aB + TILE16K + rbB1 + ((segA ^ rxB) << 4);
                    ldsm4(bh[0], sb0); ldsm4(bh[1], sb1);
                    ldsm4(bl[0], sb0 + TILE16K); ldsm4(bl[1], sb1 + TILE16K);
                }
#pragma unroll
                for (int j = 0; j < 4; j++) {
                    const int g = j >> 1, o = j & 1;
                    mma16816(acc[0][j], a0, bh[g][o], bh[g][2 + o]);
                    mma16816(acc[0][j], a0, bl[g][o], bl[g][2 + o]);
                    mma16816(acc[1][j], a1, bh[g][o], bh[g][2 + o]);
                    mma16816(acc[1][j], a1, bl[g][o], bl[g][2 + o]);
                }
            }
            __syncthreads();
        }

        // ============ epilogue: +embW[x], relu, fp16 store h, stats ========
        {
            const int cb = n0 + nw * 32 + (lane & 3) * 2;
            float csum[4][2], csq[4][2];
#pragma unroll
            for (int j = 0; j < 4; j++) {
                csum[j][0] = 0.f; csum[j][1] = 0.f;
                csq[j][0] = 0.f;  csq[j][1] = 0.f;
            }
#pragma unroll
            for (int mt = 0; mt < 2; mt++) {
#pragma unroll
                for (int rr = 0; rr < 2; rr++) {
                    const int lrow = mw * 32 + mt * 16 + rr * 8 + (lane >> 2);
                    const int row = m0 + lrow;
                    const float* ew = g_embW + (size_t)xs[lrow] * NHID;
                    uint16_t* dH = hn + (size_t)row * NHID;
#pragma unroll
                    for (int j = 0; j < 4; j++) {
                        const int col = cb + j * 8;
                        float2 e = *(const float2*)(ew + col);
                        float v0 = fmaxf(acc[mt][j][rr * 2 + 0] + e.x, 0.f);
                        float v1 = fmaxf(acc[mt][j][rr * 2 + 1] + e.y, 0.f);
                        __half2 hv = __floats2half2_rn(v0, v1);
                        *(uint32_t*)(dH + col) = *(uint32_t*)&hv;
                        csum[j][0] += v0; csum[j][1] += v1;
                        csq[j][0] = fmaf(v0, v0, csq[j][0]);
                        csq[j][1] = fmaf(v1, v1, csq[j][1]);
                    }
                }
            }
#pragma unroll
            for (int j = 0; j < 4; j++) {
                float s0 = csum[j][0], s1 = csum[j][1];
                float q0 = csq[j][0], q1 = csq[j][1];
                s0 += __shfl_down_sync(~0u, s0, 16);
                s1 += __shfl_down_sync(~0u, s1, 16);
                q0 += __shfl_down_sync(~0u, q0, 16);
                q1 += __shfl_down_sync(~0u, q1, 16);
                s0 += __shfl_down_sync(~0u, s0, 8);
                s1 += __shfl_down_sync(~0u, s1, 8);
                q0 += __shfl_down_sync(~0u, q0, 8);
                q1 += __shfl_down_sync(~0u, q1, 8);
                s0 += __shfl_down_sync(~0u, s0, 4);
                s1 += __shfl_down_sync(~0u, s1, 4);
                q0 += __shfl_down_sync(~0u, q0, 4);
                q1 += __shfl_down_sync(~0u, q1, 4);
                if (lane < 4) {
                    const int col = n0 + nw * 32 + j * 8 + lane * 2;
                    atomicAdd(&g_sum3[sp][col], s0);
                    atomicAdd(&g_sum3[sp][col + 1], s1);
                    atomicAdd(&g_sumsq3[sp][col], q0);
                    atomicAdd(&g_sumsq3[sp][col + 1], q1);
                }
            }
        }

        gridbar(epoch);

        // ======== post-bar: zero stale stats; scale/shift; xs(t+1) =========
        {
            const int st = (t + 2) % 3;   // == (t-1) mod 3
            if (tid < 8) g_sum3[st][b * 8 + tid] = 0.f;
            else if (tid < 16) g_sumsq3[st][b * 8 + tid - 8] = 0.f;
#pragma unroll
            for (int u = 0; u < 2; u++) {
                const int c = tid + u * NTHR;
                float mu = g_sum3[sp][c] * (1.f / NB);
                float var = g_sumsq3[sp][c] * (1.f / NB) - mu * mu;
                float rs = rsqrtf(var + EPS);
                float sc = rs * sGa[c];
                sS[c] = sc;
                sH[c] = sBe[c] - mu * sc;
            }
            if (t < NT - 1 && tid < 128) xs[tid] = x[(m0 + tid) * NT + t + 1];
        }
        __syncthreads();

        // prefetch chunk 0 of step t+1 (hidden under phase 3)
        if (t < NT - 1) {
            stage_chunk(buf0, hn, m0, n0, 0, tid);
            CP_COMMIT();
        }

        // ============ phase 3: output GEMM (16 rows/block) ============
        {
            const int om0 = b * 16;
            const int v31 = lane;
            const int rg = wid;           // 0..15: one row per warp
            float oa0 = 0.f, oa1 = 0.f, oa2 = 0.f, oa3 = 0.f;

            for (int k0 = 0; k0 < NHID; k0 += 64) {
                {
                    const int i0 = tid * 2;
                    const int rr = i0 >> 6, kk = i0 & 63;
                    const uint16_t* ph = hn + (size_t)(om0 + rr) * NHID + k0 + kk;
                    uint32_t uh = *(const uint32_t*)ph;
                    float2 fh = __half22float2(*(__half2*)&uh);
                    hsB[rr * 64 + kk]     = fmaf(fh.x, sS[k0 + kk],     sH[k0 + kk]);
                    hsB[rr * 64 + kk + 1] = fmaf(fh.y, sS[k0 + kk + 1], sH[k0 + kk + 1]);
                }
                for (int idx = tid; idx < 64 * 32; idx += NTHR) {
                    int kk = idx & 63;
                    int vv = idx >> 6;
                    wsB[kk * 33 + vv] = (vv < NVOC) ? Who[vv * NHID + k0 + kk] : 0.f;
                }
                __syncthreads();
                const float* hrow = hsB + rg * 64;
#pragma unroll
                for (int kk = 0; kk < 64; kk += 4) {
                    float4 h4 = *(const float4*)(hrow + kk);
                    oa0 = fmaf(h4.x, wsB[(kk + 0) * 33 + v31], oa0);
                    oa1 = fmaf(h4.y, wsB[(kk + 1) * 33 + v31], oa1);
                    oa2 = fmaf(h4.z, wsB[(kk + 2) * 33 + v31], oa2);
                    oa3 = fmaf(h4.w, wsB[(kk + 3) * 33 + v31], oa3);
                }
                __syncthreads();
            }

            if (v31 < NVOC) {
                size_t orow = om0 + rg;
                out[orow * (size_t)(NT * NVOC) + (size_t)t * NVOC + v31] =
                    (oa0 + oa1) + (oa2 + oa3) + bho[v31];
            }
        }
    }
}

// ---------------------------------------------------------------------------
extern "C" void kernel_launch(void* const* d_in, const int* in_sizes, int n_in,
                              void* d_out, int out_size)
{
    const int*   x     = (const int*)d_in[0];
    const float* emb   = (const float*)d_in[1];
    const float* Whh   = (const float*)d_in[2];
    const float* bhh   = (const float*)d_in[3];
    const float* Who   = (const float*)d_in[4];
    const float* bho   = (const float*)d_in[5];
    const float* gamma = (const float*)d_in[6];
    const float* beta  = (const float*)d_in[7];
    float* out = (float*)d_out;

    cudaFuncSetAttribute(k_persist, cudaFuncAttributeMaxDynamicSharedMemorySize,
                         SMEM_TOTAL);

    k_init<<<1024, 256>>>(Whh, emb, bhh);
    k_persist<<<NBLK, NTHR, SMEM_TOTAL>>>(x, Who, bho, gamma, beta, out);
}

// round 9
// speedup vs baseline: 3.1274x; 1.2152x over previous
#include <cuda_runtime.h>
#include <cuda_fp16.h>
#include <cstdint>

#define NB   2048
#define NT   512
#define NHID 1024
#define NVOC 31
#define EPS  1e-5f
#define NBLK 128
#define NTHR 512

#define KCH     64
#define NCHUNK  (NHID / KCH)        // 16
#define TILE16K 16384               // one 128x64 fp16 tile, 128B rows
#define BUFSZ   (2 * TILE16K)       // A, B

// smem layout (dynamic)
#define OFF_XS   0                  // 128 ints   -> 512
#define OFF_SS   512                // scale 1024f -> 4608
#define OFF_SH   4608               // shift 1024f -> 8704
#define OFF_GA   8704               // gamma      -> 12800
#define OFF_BE   12800              // beta       -> 16896
#define OFF_HS   16896              // 16x64 f    -> 20992
#define OFF_WS   20992              // 64x33 f    -> 29440
#define OFF_BUF  29440              // 128B aligned
#define SMEM_TOTAL (OFF_BUF + 2 * BUFSZ)   // 94976

// ---- persistent device state ----
__device__ __align__(16) uint16_t g_h16[2][NB * NHID];  // h fp16
__device__ __align__(16) uint16_t g_Wh[NHID * NHID];    // W_hh fp16
__device__ __align__(16) float    g_embW[NVOC * NHID];  // emb @ W^T + b_hh
__device__ __align__(16) float    g_sum3[3][NHID];
__device__ __align__(16) float    g_sumsq3[3][NHID];
__device__ unsigned g_count;

// ============================ PTX helpers ============================
__device__ __forceinline__ uint32_t smem_to_u32(const void* p) {
    uint32_t a;
    asm("{ .reg .u64 t; cvta.to.shared.u64 t, %1; cvt.u32.u64 %0, t; }"
        : "=r"(a) : "l"(p));
    return a;
}
#define CP16(dst, src) \
    asm volatile("cp.async.cg.shared.global [%0], [%1], 16;" \
                 :: "r"(dst), "l"(src) : "memory")
#define CP_COMMIT() asm volatile("cp.async.commit_group;" ::: "memory")
#define CP_WAIT(n)  asm volatile("cp.async.wait_group %0;" :: "n"(n) : "memory")

__device__ __forceinline__ void ldsm4(uint32_t* r, uint32_t addr) {
    asm volatile("ldmatrix.sync.aligned.m8n8.x4.shared.b16 {%0,%1,%2,%3}, [%4];"
                 : "=r"(r[0]), "=r"(r[1]), "=r"(r[2]), "=r"(r[3]) : "r"(addr));
}
__device__ __forceinline__ void mma16816(float* c, const uint32_t* a,
                                         uint32_t b0, uint32_t b1) {
    asm volatile(
        "mma.sync.aligned.m16n8k16.row.col.f32.f16.f16.f32 "
        "{%0,%1,%2,%3}, {%4,%5,%6,%7}, {%8,%9}, {%0,%1,%2,%3};"
        : "+f"(c[0]), "+f"(c[1]), "+f"(c[2]), "+f"(c[3])
        : "r"(a[0]), "r"(a[1]), "r"(a[2]), "r"(a[3]), "r"(b0), "r"(b1));
}

// ---------------------------------------------------------------------------
// init: zero h[0]; W_hh -> fp16; embW = emb@W^T + b_hh
// ---------------------------------------------------------------------------
__global__ void k_init(const float* __restrict__ W, const float* __restrict__ emb,
                       const float* __restrict__ bhh) {
    int gid = blockIdx.x * blockDim.x + threadIdx.x;
    int stride = gridDim.x * blockDim.x;
    uint32_t* zA = (uint32_t*)g_h16[0];
    for (int i = gid; i < NB * NHID / 2; i += stride) zA[i] = 0u;
    for (int i = gid; i < NHID * NHID; i += stride)
        g_Wh[i] = __half_as_ushort(__float2half_rn(W[i]));
    if (gid < NVOC * NHID) {
        int v = gid >> 10, n = gid & (NHID - 1);
        const float4* er = (const float4*)(emb + (size_t)v * NHID);
        const float4* wr = (const float4*)(W + (size_t)n * NHID);
        float s0 = 0.f, s1 = 0.f, s2 = 0.f, s3 = 0.f;
        for (int k = 0; k < NHID / 4; k++) {
            float4 e = er[k], w = wr[k];
            s0 = fmaf(e.x, w.x, s0); s1 = fmaf(e.y, w.y, s1);
            s2 = fmaf(e.z, w.z, s2); s3 = fmaf(e.w, w.w, s3);
        }
        g_embW[gid] = (s0 + s1) + (s2 + s3) + bhh[n];
    }
    if (gid < NHID) {
        for (int r = 0; r < 3; r++) { g_sum3[r][gid] = 0.f; g_sumsq3[r][gid] = 0.f; }
    }
    if (gid == 0) g_count = 0u;
}

// ---------------------------------------------------------------------------
// grid barrier (all 128 blocks resident)
// ---------------------------------------------------------------------------
__device__ __forceinline__ void gridbar(unsigned& epoch) {
    __syncthreads();
    epoch += NBLK;
    if (threadIdx.x == 0) {
        __threadfence();
        atomicAdd(&g_count, 1u);
        while (*(volatile unsigned*)&g_count < epoch) { }
        __threadfence();
    }
    __syncthreads();
}

// stage one 64-K chunk: A (h fp16), B (W fp16); SW128-swizzled; 512 threads
__device__ __forceinline__ void stage_chunk(
    uint32_t dstbase, const uint16_t* __restrict__ hsrc,
    int m0, int n0, int k0, int tid)
{
    const int r = tid >> 2;                 // 0..127
    const int s0 = (tid & 3) * 2;
    const uint32_t rb = (uint32_t)r * 128;
    const uint32_t rx = (uint32_t)(r & 7);
    const uint16_t* sA = hsrc + (size_t)(m0 + r) * NHID + k0;
    const uint16_t* sB = g_Wh + (size_t)(n0 + r) * NHID + k0;
#pragma unroll
    for (int u = 0; u < 2; u++) {
        uint32_t s = (uint32_t)(s0 + u);
        uint32_t d = dstbase + rb + ((s ^ rx) << 4);
        CP16(d,           sA + s * 8);
        CP16(d + TILE16K, sB + s * 8);
    }
}

// ---------------------------------------------------------------------------
// persistent kernel: 512 threads, 16 warps, warp tile 32x32
// ---------------------------------------------------------------------------
__global__ __launch_bounds__(NTHR, 1) void k_persist(
    const int* __restrict__ x,
    const float* __restrict__ Who, const float* __restrict__ bho,
    const float* __restrict__ gamma, const float* __restrict__ beta,
    float* __restrict__ out)
{
    extern __shared__ char smem[];
    const uint32_t sb = smem_to_u32(smem);
    const int tid = threadIdx.x;
    const int wid = tid >> 5;
    const int lane = tid & 31;
    const int b = blockIdx.x;
    const int n0 = (b & 7) * 128;
    const int m0 = (b >> 3) * 128;
    const int mw = wid >> 2;        // 0..3 : 32-row slice
    const int nw = wid & 3;         // 0..3 : 32-col slice

    int* xs = (int*)(smem + OFF_XS);
    float* sS = (float*)(smem + OFF_SS);
    float* sH = (float*)(smem + OFF_SH);
    float* sGa = (float*)(smem + OFF_GA);
    float* sBe = (float*)(smem + OFF_BE);
    float* hsB = (float*)(smem + OFF_HS);
    float* wsB = (float*)(smem + OFF_WS);
    const uint32_t buf0 = sb + OFF_BUF;

    // ldmatrix per-lane constants
    const uint32_t raA0 = (uint32_t)(mw * 32 + (lane & 15)) * 128;
    const uint32_t raA1 = raA0 + 16 * 128;
    const uint32_t rxA = (uint32_t)(lane & 7);
    const uint32_t rbB0 = (uint32_t)(nw * 32 + (lane & 15)) * 128;
    const uint32_t rbB1 = rbB0 + 16 * 128;
    const uint32_t rxB = rxA;
    const int hl = lane >> 4;

    sGa[tid] = gamma[tid]; sGa[tid + 512] = gamma[tid + 512];
    sBe[tid] = beta[tid];  sBe[tid + 512] = beta[tid + 512];
    if (tid < 128) xs[tid] = x[(m0 + tid) * NT + 0];
    __syncthreads();

    stage_chunk(buf0, g_h16[0], m0, n0, 0, tid);
    CP_COMMIT();

    unsigned epoch = 0;

    for (int t = 0; t < NT; t++) {
        const int cur = t & 1;
        const uint16_t* hp = g_h16[cur];
        uint16_t* hn = g_h16[cur ^ 1];
        const int sp = t % 3;

        // ============ phase 1: h @ W^T via fp16 single-product mma ==========
        float acc[2][4][4];
#pragma unroll
        for (int mt = 0; mt < 2; mt++)
#pragma unroll
            for (int j = 0; j < 4; j++)
#pragma unroll
                for (int q = 0; q < 4; q++) acc[mt][j][q] = 0.f;

        for (int c = 0; c < NCHUNK; c++) {
            const int p = c & 1;
            if (c < NCHUNK - 1) {
                stage_chunk(buf0 + (p ^ 1) * BUFSZ, hp, m0, n0, (c + 1) * KCH, tid);
                CP_COMMIT();
                CP_WAIT(1);
            } else {
                CP_WAIT(0);
            }
            __syncthreads();

            const uint32_t aB = buf0 + p * BUFSZ;
#pragma unroll
            for (int kt = 0; kt < 4; kt++) {
                const uint32_t segA = (uint32_t)(kt * 2 + hl);
                uint32_t a0[4], a1[4];
                {
                    uint32_t sa0 = aB + raA0 + ((segA ^ rxA) << 4);
                    uint32_t sa1 = aB + raA1 + ((segA ^ rxA) << 4);
                    ldsm4(a0, sa0); ldsm4(a1, sa1);
                }
                uint32_t bh[2][4];
                {
                    uint32_t sb0 = aB + TILE16K + rbB0 + ((segA ^ rxB) << 4);
                    uint32_t sb1 = aB + TILE16K + rbB1 + ((segA ^ rxB) << 4);
                    ldsm4(bh[0], sb0); ldsm4(bh[1], sb1);
                }
#pragma unroll
                for (int j = 0; j < 4; j++) {
                    const int g = j >> 1, o = j & 1;
                    mma16816(acc[0][j], a0, bh[g][o], bh[g][2 + o]);
                    mma16816(acc[1][j], a1, bh[g][o], bh[g][2 + o]);
                }
            }
            __syncthreads();
        }

        // ============ epilogue: +embW[x], relu, fp16 store h, stats ========
        {
            const int cb = n0 + nw * 32 + (lane & 3) * 2;
            float csum[4][2], csq[4][2];
#pragma unroll
            for (int j = 0; j < 4; j++) {
                csum[j][0] = 0.f; csum[j][1] = 0.f;
                csq[j][0] = 0.f;  csq[j][1] = 0.f;
            }
#pragma unroll
            for (int mt = 0; mt < 2; mt++) {
#pragma unroll
                for (int rr = 0; rr < 2; rr++) {
                    const int lrow = mw * 32 + mt * 16 + rr * 8 + (lane >> 2);
                    const int row = m0 + lrow;
                    const float* ew = g_embW + (size_t)xs[lrow] * NHID;
                    uint16_t* dH = hn + (size_t)row * NHID;
#pragma unroll
                    for (int j = 0; j < 4; j++) {
                        const int col = cb + j * 8;
                        float2 e = *(const float2*)(ew + col);
                        float v0 = fmaxf(acc[mt][j][rr * 2 + 0] + e.x, 0.f);
                        float v1 = fmaxf(acc[mt][j][rr * 2 + 1] + e.y, 0.f);
                        __half2 hv = __floats2half2_rn(v0, v1);
                        *(uint32_t*)(dH + col) = *(uint32_t*)&hv;
                        csum[j][0] += v0; csum[j][1] += v1;
                        csq[j][0] = fmaf(v0, v0, csq[j][0]);
                        csq[j][1] = fmaf(v1, v1, csq[j][1]);
                    }
                }
            }
#pragma unroll
            for (int j = 0; j < 4; j++) {
                float s0 = csum[j][0], s1 = csum[j][1];
                float q0 = csq[j][0], q1 = csq[j][1];
                s0 += __shfl_down_sync(~0u, s0, 16);
                s1 += __shfl_down_sync(~0u, s1, 16);
                q0 += __shfl_down_sync(~0u, q0, 16);
                q1 += __shfl_down_sync(~0u, q1, 16);
                s0 += __shfl_down_sync(~0u, s0, 8);
                s1 += __shfl_down_sync(~0u, s1, 8);
                q0 += __shfl_down_sync(~0u, q0, 8);
                q1 += __shfl_down_sync(~0u, q1, 8);
                s0 += __shfl_down_sync(~0u, s0, 4);
                s1 += __shfl_down_sync(~0u, s1, 4);
                q0 += __shfl_down_sync(~0u, q0, 4);
                q1 += __shfl_down_sync(~0u, q1, 4);
                if (lane < 4) {
                    const int col = n0 + nw * 32 + j * 8 + lane * 2;
                    atomicAdd(&g_sum3[sp][col], s0);
                    atomicAdd(&g_sum3[sp][col + 1], s1);
                    atomicAdd(&g_sumsq3[sp][col], q0);
                    atomicAdd(&g_sumsq3[sp][col + 1], q1);
                }
            }
        }

        gridbar(epoch);

        // ======== post-bar: zero stale stats; scale/shift; xs(t+1) =========
        {
            const int st = (t + 2) % 3;   // == (t-1) mod 3
            if (tid < 8) g_sum3[st][b * 8 + tid] = 0.f;
            else if (tid < 16) g_sumsq3[st][b * 8 + tid - 8] = 0.f;
#pragma unroll
            for (int u = 0; u < 2; u++) {
                const int c = tid + u * NTHR;
                float mu = g_sum3[sp][c] * (1.f / NB);
                float var = g_sumsq3[sp][c] * (1.f / NB) - mu * mu;
                float rs = rsqrtf(var + EPS);
                float sc = rs * sGa[c];
                sS[c] = sc;
                sH[c] = sBe[c] - mu * sc;
            }
            if (t < NT - 1 && tid < 128) xs[tid] = x[(m0 + tid) * NT + t + 1];
        }
        __syncthreads();

        // prefetch chunk 0 of step t+1 (hidden under phase 3)
        if (t < NT - 1) {
            stage_chunk(buf0, hn, m0, n0, 0, tid);
            CP_COMMIT();
        }

        // ============ phase 3: output GEMM (16 rows/block) ============
        {
            const int om0 = b * 16;
            const int v31 = lane;
            const int rg = wid;           // 0..15: one row per warp
            float oa0 = 0.f, oa1 = 0.f, oa2 = 0.f, oa3 = 0.f;

            for (int k0 = 0; k0 < NHID; k0 += 64) {
                {
                    const int i0 = tid * 2;
                    const int rr = i0 >> 6, kk = i0 & 63;
                    const uint16_t* ph = hn + (size_t)(om0 + rr) * NHID + k0 + kk;
                    uint32_t uh = *(const uint32_t*)ph;
                    float2 fh = __half22float2(*(__half2*)&uh);
                    hsB[rr * 64 + kk]     = fmaf(fh.x, sS[k0 + kk],     sH[k0 + kk]);
                    hsB[rr * 64 + kk + 1] = fmaf(fh.y, sS[k0 + kk + 1], sH[k0 + kk + 1]);
                }
                for (int idx = tid; idx < 64 * 32; idx += NTHR) {
                    int kk = idx & 63;
                    int vv = idx >> 6;
                    wsB[kk * 33 + vv] = (vv < NVOC) ? Who[vv * NHID + k0 + kk] : 0.f;
                }
                __syncthreads();
                const float* hrow = hsB + rg * 64;
#pragma unroll
                for (int kk = 0; kk < 64; kk += 4) {
                    float4 h4 = *(const float4*)(hrow + kk);
                    oa0 = fmaf(h4.x, wsB[(kk + 0) * 33 + v31], oa0);
                    oa1 = fmaf(h4.y, wsB[(kk + 1) * 33 + v31], oa1);
                    oa2 = fmaf(h4.z, wsB[(kk + 2) * 33 + v31], oa2);
                    oa3 = fmaf(h4.w, wsB[(kk + 3) * 33 + v31], oa3);
                }
                __syncthreads();
            }

            if (v31 < NVOC) {
                size_t orow = om0 + rg;
                out[orow * (size_t)(NT * NVOC) + (size_t)t * NVOC + v31] =
                    (oa0 + oa1) + (oa2 + oa3) + bho[v31];
            }
        }
    }
}

// ---------------------------------------------------------------------------
extern "C" void kernel_launch(void* const* d_in, const int* in_sizes, int n_in,
                              void* d_out, int out_size)
{
    const int*   x     = (const int*)d_in[0];
    const float* emb   = (const float*)d_in[1];
    const float* Whh   = (const float*)d_in[2];
    const float* bhh   = (const float*)d_in[3];
    const float* Who   = (const float*)d_in[4];
    const float* bho   = (const float*)d_in[5];
    const float* gamma = (const float*)d_in[6];
    const float* beta  = (const float*)d_in[7];
    float* out = (float*)d_out;

    cudaFuncSetAttribute(k_persist, cudaFuncAttributeMaxDynamicSharedMemorySize,
                         SMEM_TOTAL);

    k_init<<<1024, 256>>>(Whh, emb, bhh);
    k_persist<<<NBLK, NTHR, SMEM_TOTAL>>>(x, Who, bho, gamma, beta, out);
}

// round 10
// speedup vs baseline: 3.4347x; 1.0983x over previous
#include <cuda_runtime.h>
#include <cuda.h>
#include <cuda_fp16.h>
#include <cstdint>

#define NB   2048
#define NT   512
#define NHID 1024
#define NVOC 31
#define EPS  1e-5f
#define NBLK 128
#define NTHR 512

#define KCH     64
#define NCHUNK  16
#define TILE16K 16384               // one 128x64 fp16 tile, 128B rows
#define STAGESZ 32768               // A tile + B tile
#define NSTAGE  4

// smem layout (dynamic)
#define OFF_MB   0                  // full[4] @ +0..31, empty[4] @ +32..63
#define OFF_XS   64                 // 128 ints -> 576
#define OFF_SS   576                // scale 1024f -> 4672
#define OFF_SH   4672               // shift -> 8768
#define OFF_GA   8768               // gamma -> 12864
#define OFF_BE   12864              // beta  -> 16960
#define OFF_HS   16960              // 16x64 f -> 21056
#define OFF_WS   21056              // 64x33 f -> 29504
#define OFF_BUF  29504
#define SMEM_TOTAL (OFF_BUF + 1024 + NSTAGE * STAGESZ)   // 161600

// ---- persistent device state ----
__device__ __align__(128) uint16_t g_h16[2][NB * NHID];  // h fp16 (TMA src)
__device__ __align__(128) uint16_t g_Wh[NHID * NHID];    // W_hh fp16 (TMA src)
__device__ __align__(16)  float    g_embW[NVOC * NHID];  // emb @ W^T + b_hh
__device__ __align__(16)  float    g_sum3[3][NHID];
__device__ __align__(16)  float    g_sumsq3[3][NHID];
__device__ unsigned g_count;

// ============================ PTX helpers ============================
__device__ __forceinline__ uint32_t smem_to_u32(const void* p) {
    uint32_t a;
    asm("{ .reg .u64 t; cvta.to.shared.u64 t, %1; cvt.u32.u64 %0, t; }"
        : "=r"(a) : "l"(p));
    return a;
}
#define MBARRIER_INIT(mb, cnt) \
    asm volatile("mbarrier.init.shared.b64 [%0], %1;" \
                 :: "r"((uint32_t)(mb)), "r"((uint32_t)(cnt)) : "memory")
#define MBARRIER_ARRIVE(mb) \
    asm volatile("mbarrier.arrive.shared.b64 _, [%0];" \
                 :: "r"((uint32_t)(mb)) : "memory")
#define MBARRIER_EXPECT_TX(mb, bytes) \
    asm volatile("mbarrier.arrive.expect_tx.shared.b64 _, [%0], %1;" \
                 :: "r"((uint32_t)(mb)), "r"((uint32_t)(bytes)) : "memory")
#define MBARRIER_WAIT_PARITY(mb, ph) do {                                   \
    uint32_t _m = (uint32_t)(mb); uint32_t _p = (uint32_t)(ph);             \
    asm volatile("{\n\t.reg .pred P1;\n\t"                                  \
        "WAIT_LOOP_%=:\n\t"                                                 \
        "mbarrier.try_wait.parity.acquire.cta.shared::cta.b64 P1, [%0], %1, 0x989680;\n\t" \
        "@P1 bra.uni WAIT_DONE_%=;\n\t"                                     \
        "bra.uni WAIT_LOOP_%=;\n\t"                                         \
        "WAIT_DONE_%=:\n\t}" :: "r"(_m), "r"(_p) : "memory");               \
} while (0)
#define FENCE_PROXY_ASYNC() asm volatile("fence.proxy.async;" ::: "memory")

__device__ __forceinline__ void ldsm4(uint32_t* r, uint32_t addr) {
    asm volatile("ldmatrix.sync.aligned.m8n8.x4.shared.b16 {%0,%1,%2,%3}, [%4];"
                 : "=r"(r[0]), "=r"(r[1]), "=r"(r[2]), "=r"(r[3]) : "r"(addr));
}
__device__ __forceinline__ void mma16816(float* c, const uint32_t* a,
                                         uint32_t b0, uint32_t b1) {
    asm volatile(
        "mma.sync.aligned.m16n8k16.row.col.f32.f16.f16.f32 "
        "{%0,%1,%2,%3}, {%4,%5,%6,%7}, {%8,%9}, {%0,%1,%2,%3};"
        : "+f"(c[0]), "+f"(c[1]), "+f"(c[2]), "+f"(c[3])
        : "r"(a[0]), "r"(a[1]), "r"(a[2]), "r"(a[3]), "r"(b0), "r"(b1));
}

// TMA issue for one 64-K chunk c (within its step): A tile (h) + B tile (W)
__device__ __forceinline__ void issue_chunk(
    uint32_t sb, uint32_t bufabs,
    const CUtensorMap* mH, const CUtensorMap* mW,
    int curbuf, int m0, int n0, int c)
{
    const int s = c & 3;
    const uint32_t pe = ((uint32_t)(c >> 2) & 1u) ^ 1u;
    MBARRIER_WAIT_PARITY(sb + OFF_MB + 32 + s * 8, pe);
    MBARRIER_EXPECT_TX(sb + OFF_MB + s * 8, STAGESZ);
    const uint32_t dA = bufabs + s * STAGESZ;
    const int k0 = c * KCH;
    asm volatile(
        "cp.async.bulk.tensor.3d.shared::cta.global.tile.mbarrier::complete_tx::bytes "
        "[%0], [%1, {%2, %3, %4}], [%5];"
        :: "r"(dA), "l"(mH), "r"(k0), "r"(m0), "r"(curbuf),
           "r"(sb + OFF_MB + s * 8) : "memory");
    asm volatile(
        "cp.async.bulk.tensor.2d.shared::cta.global.tile.mbarrier::complete_tx::bytes "
        "[%0], [%1, {%2, %3}], [%4];"
        :: "r"(dA + TILE16K), "l"(mW), "r"(k0), "r"(n0),
           "r"(sb + OFF_MB + s * 8) : "memory");
}

// ---------------------------------------------------------------------------
// init: zero h[0]; W_hh -> fp16; embW = emb@W^T + b_hh
// ---------------------------------------------------------------------------
__global__ void k_init(const float* __restrict__ W, const float* __restrict__ emb,
                       const float* __restrict__ bhh) {
    int gid = blockIdx.x * blockDim.x + threadIdx.x;
    int stride = gridDim.x * blockDim.x;
    uint32_t* zA = (uint32_t*)g_h16[0];
    for (int i = gid; i < NB * NHID / 2; i += stride) zA[i] = 0u;
    for (int i = gid; i < NHID * NHID; i += stride)
        g_Wh[i] = __half_as_ushort(__float2half_rn(W[i]));
    if (gid < NVOC * NHID) {
        int v = gid >> 10, n = gid & (NHID - 1);
        const float4* er = (const float4*)(emb + (size_t)v * NHID);
        const float4* wr = (const float4*)(W + (size_t)n * NHID);
        float s0 = 0.f, s1 = 0.f, s2 = 0.f, s3 = 0.f;
        for (int k = 0; k < NHID / 4; k++) {
            float4 e = er[k], w = wr[k];
            s0 = fmaf(e.x, w.x, s0); s1 = fmaf(e.y, w.y, s1);
            s2 = fmaf(e.z, w.z, s2); s3 = fmaf(e.w, w.w, s3);
        }
        g_embW[gid] = (s0 + s1) + (s2 + s3) + bhh[n];
    }
    if (gid < NHID) {
        for (int r = 0; r < 3; r++) { g_sum3[r][gid] = 0.f; g_sumsq3[r][gid] = 0.f; }
    }
    if (gid == 0) g_count = 0u;
}

// ---------------------------------------------------------------------------
// grid barrier (all 128 blocks resident) + async-proxy fence
// ---------------------------------------------------------------------------
__device__ __forceinline__ void gridbar(unsigned& epoch) {
    __syncthreads();
    epoch += NBLK;
    if (threadIdx.x == 0) {
        __threadfence();
        FENCE_PROXY_ASYNC();
        atomicAdd(&g_count, 1u);
        while (*(volatile unsigned*)&g_count < epoch) { }
        __threadfence();
    }
    __syncthreads();
}

// ---------------------------------------------------------------------------
// persistent kernel: 512 threads, 16 warps, warp tile 32x32
// ---------------------------------------------------------------------------
__global__ __launch_bounds__(NTHR, 1) void k_persist(
    const __grid_constant__ CUtensorMap mapH,
    const __grid_constant__ CUtensorMap mapW,
    const int* __restrict__ x,
    const float* __restrict__ Who, const float* __restrict__ bho,
    const float* __restrict__ gamma, const float* __restrict__ beta,
    float* __restrict__ out)
{
    extern __shared__ char smem[];
    const uint32_t sb = smem_to_u32(smem);
    const int tid = threadIdx.x;
    const int wid = tid >> 5;
    const int lane = tid & 31;
    const int b = blockIdx.x;
    const int n0 = (b & 7) * 128;
    const int m0 = (b >> 3) * 128;
    const int mw = wid >> 2;        // 0..3 : 32-row slice
    const int nw = wid & 3;         // 0..3 : 32-col slice

    int* xs = (int*)(smem + OFF_XS);
    float* sS = (float*)(smem + OFF_SS);
    float* sH = (float*)(smem + OFF_SH);
    float* sGa = (float*)(smem + OFF_GA);
    float* sBe = (float*)(smem + OFF_BE);
    float* hsB = (float*)(smem + OFF_HS);
    float* wsB = (float*)(smem + OFF_WS);
    const uint32_t bufabs = (sb + OFF_BUF + 1023) & ~1023u;

    // ldmatrix per-lane constants
    const uint32_t raA0 = (uint32_t)(mw * 32 + (lane & 15)) * 128;
    const uint32_t raA1 = raA0 + 16 * 128;
    const uint32_t rxA = (uint32_t)(lane & 7);
    const uint32_t rbB0 = (uint32_t)(nw * 32 + (lane & 15)) * 128;
    const uint32_t rbB1 = rbB0 + 16 * 128;
    const uint32_t rxB = rxA;
    const int hl = lane >> 4;

    // mbarrier init + preload gamma/beta + xs(0)
    if (tid == 0) {
        for (int s = 0; s < NSTAGE; s++) {
            MBARRIER_INIT(sb + OFF_MB + s * 8, 1);        // full: tx-based
            MBARRIER_INIT(sb + OFF_MB + 32 + s * 8, 16);  // empty: 16 warps
        }
        FENCE_PROXY_ASYNC();
    }
    sGa[tid] = gamma[tid]; sGa[tid + 512] = gamma[tid + 512];
    sBe[tid] = beta[tid];  sBe[tid + 512] = beta[tid + 512];
    if (tid < 128) xs[tid] = x[(m0 + tid) * NT + 0];
    __syncthreads();

    if (tid == 0)
        for (int c = 0; c < 3; c++)
            issue_chunk(sb, bufabs, &mapH, &mapW, 0, m0, n0, c);

    unsigned epoch = 0;

    for (int t = 0; t < NT; t++) {
        const int cur = t & 1;
        uint16_t* hn = g_h16[cur ^ 1];
        const int sp = t % 3;

        // ============ phase 1: h @ W^T via fp16 mma, TMA-fed ============
        float acc[2][4][4];
#pragma unroll
        for (int mt = 0; mt < 2; mt++)
#pragma unroll
            for (int j = 0; j < 4; j++)
#pragma unroll
                for (int q = 0; q < 4; q++) acc[mt][j][q] = 0.f;

        for (int c = 0; c < NCHUNK; c++) {
            if (tid == 0 && c + 3 < NCHUNK)
                issue_chunk(sb, bufabs, &mapH, &mapW, cur, m0, n0, c + 3);
            const int s = c & 3;
            MBARRIER_WAIT_PARITY(sb + OFF_MB + s * 8, (uint32_t)((c >> 2) & 1));
            const uint32_t aB = bufabs + s * STAGESZ;
#pragma unroll
            for (int kt = 0; kt < 4; kt++) {
                const uint32_t segA = (uint32_t)(kt * 2 + hl);
                uint32_t a0[4], a1[4];
                {
                    uint32_t sa0 = aB + raA0 + ((segA ^ rxA) << 4);
                    uint32_t sa1 = aB + raA1 + ((segA ^ rxA) << 4);
                    ldsm4(a0, sa0); ldsm4(a1, sa1);
                }
                uint32_t bh[2][4];
                {
                    uint32_t sb0 = aB + TILE16K + rbB0 + ((segA ^ rxB) << 4);
                    uint32_t sb1 = aB + TILE16K + rbB1 + ((segA ^ rxB) << 4);
                    ldsm4(bh[0], sb0); ldsm4(bh[1], sb1);
                }
#pragma unroll
                for (int j = 0; j < 4; j++) {
                    const int g = j >> 1, o = j & 1;
                    mma16816(acc[0][j], a0, bh[g][o], bh[g][2 + o]);
                    mma16816(acc[1][j], a1, bh[g][o], bh[g][2 + o]);
                }
            }
            __syncwarp();
            if (lane == 0) MBARRIER_ARRIVE(sb + OFF_MB + 32 + s * 8);
        }

        // ============ epilogue: +embW[x], relu, fp16 store h, stats ========
        {
            const int cb = n0 + nw * 32 + (lane & 3) * 2;
            float csum[4][2], csq[4][2];
#pragma unroll
            for (int j = 0; j < 4; j++) {
                csum[j][0] = 0.f; csum[j][1] = 0.f;
                csq[j][0] = 0.f;  csq[j][1] = 0.f;
            }
#pragma unroll
            for (int mt = 0; mt < 2; mt++) {
#pragma unroll
                for (int rr = 0; rr < 2; rr++) {
                    const int lrow = mw * 32 + mt * 16 + rr * 8 + (lane >> 2);
                    const int row = m0 + lrow;
                    const float* ew = g_embW + (size_t)xs[lrow] * NHID;
                    uint16_t* dH = hn + (size_t)row * NHID;
#pragma unroll
                    for (int j = 0; j < 4; j++) {
                        const int col = cb + j * 8;
                        float2 e = *(const float2*)(ew + col);
                        float v0 = fmaxf(acc[mt][j][rr * 2 + 0] + e.x, 0.f);
                        float v1 = fmaxf(acc[mt][j][rr * 2 + 1] + e.y, 0.f);
                        __half2 hv = __floats2half2_rn(v0, v1);
                        *(uint32_t*)(dH + col) = *(uint32_t*)&hv;
                        csum[j][0] += v0; csum[j][1] += v1;
                        csq[j][0] = fmaf(v0, v0, csq[j][0]);
                        csq[j][1] = fmaf(v1, v1, csq[j][1]);
                    }
                }
            }
#pragma unroll
            for (int j = 0; j < 4; j++) {
                float s0 = csum[j][0], s1 = csum[j][1];
                float q0 = csq[j][0], q1 = csq[j][1];
                s0 += __shfl_down_sync(~0u, s0, 16);
                s1 += __shfl_down_sync(~0u, s1, 16);
                q0 += __shfl_down_sync(~0u, q0, 16);
                q1 += __shfl_down_sync(~0u, q1, 16);
                s0 += __shfl_down_sync(~0u, s0, 8);
                s1 += __shfl_down_sync(~0u, s1, 8);
                q0 += __shfl_down_sync(~0u, q0, 8);
                q1 += __shfl_down_sync(~0u, q1, 8);
                s0 += __shfl_down_sync(~0u, s0, 4);
                s1 += __shfl_down_sync(~0u, s1, 4);
                q0 += __shfl_down_sync(~0u, q0, 4);
                q1 += __shfl_down_sync(~0u, q1, 4);
                if (lane < 4) {
                    const int col = n0 + nw * 32 + j * 8 + lane * 2;
                    atomicAdd(&g_sum3[sp][col], s0);
                    atomicAdd(&g_sum3[sp][col + 1], s1);
                    atomicAdd(&g_sumsq3[sp][col], q0);
                    atomicAdd(&g_sumsq3[sp][col + 1], q1);
                }
            }
        }

        gridbar(epoch);

        // prefetch chunks 0..2 of step t+1 (h(t+1) now globally visible)
        if (t < NT - 1 && tid == 0)
            for (int c = 0; c < 3; c++)
                issue_chunk(sb, bufabs, &mapH, &mapW, cur ^ 1, m0, n0, c);

        // ======== post-bar: zero stale stats; scale/shift; xs(t+1) =========
        {
            const int st = (t + 2) % 3;   // == (t-1) mod 3
            if (tid < 8) g_sum3[st][b * 8 + tid] = 0.f;
            else if (tid < 16) g_sumsq3[st][b * 8 + tid - 8] = 0.f;
#pragma unroll
            for (int u = 0; u < 2; u++) {
                const int c = tid + u * NTHR;
                float mu = g_sum3[sp][c] * (1.f / NB);
                float var = g_sumsq3[sp][c] * (1.f / NB) - mu * mu;
                float rs = rsqrtf(var + EPS);
                float sc = rs * sGa[c];
                sS[c] = sc;
                sH[c] = sBe[c] - mu * sc;
            }
            if (t < NT - 1 && tid < 128) xs[tid] = x[(m0 + tid) * NT + t + 1];
        }
        __syncthreads();

        // ============ phase 3: output GEMM (16 rows/block) ============
        {
            const int om0 = b * 16;
            const int v31 = lane;
            const int rg = wid;           // 0..15: one row per warp
            float oa0 = 0.f, oa1 = 0.f, oa2 = 0.f, oa3 = 0.f;

            for (int k0 = 0; k0 < NHID; k0 += 64) {
                {
                    const int i0 = tid * 2;
                    const int rr = i0 >> 6, kk = i0 & 63;
                    const uint16_t* ph = hn + (size_t)(om0 + rr) * NHID + k0 + kk;
                    uint32_t uh = *(const uint32_t*)ph;
                    float2 fh = __half22float2(*(__half2*)&uh);
                    hsB[rr * 64 + kk]     = fmaf(fh.x, sS[k0 + kk],     sH[k0 + kk]);
                    hsB[rr * 64 + kk + 1] = fmaf(fh.y, sS[k0 + kk + 1], sH[k0 + kk + 1]);
                }
                for (int idx = tid; idx < 64 * 32; idx += NTHR) {
                    int kk = idx & 63;
                    int vv = idx >> 6;
                    wsB[kk * 33 + vv] = (vv < NVOC) ? Who[vv * NHID + k0 + kk] : 0.f;
                }
                __syncthreads();
                const float* hrow = hsB + rg * 64;
#pragma unroll
                for (int kk = 0; kk < 64; kk += 4) {
                    float4 h4 = *(const float4*)(hrow + kk);
                    oa0 = fmaf(h4.x, wsB[(kk + 0) * 33 + v31], oa0);
                    oa1 = fmaf(h4.y, wsB[(kk + 1) * 33 + v31], oa1);
                    oa2 = fmaf(h4.z, wsB[(kk + 2) * 33 + v31], oa2);
                    oa3 = fmaf(h4.w, wsB[(kk + 3) * 33 + v31], oa3);
                }
                __syncthreads();
            }

            if (v31 < NVOC) {
                size_t orow = om0 + rg;
                out[orow * (size_t)(NT * NVOC) + (size_t)t * NVOC + v31] =
                    (oa0 + oa1) + (oa2 + oa3) + bho[v31];
            }
        }
    }
}

// ---------------------------------------------------------------------------
typedef CUresult (CUDAAPI *PFN_tmap_enc)(
    CUtensorMap*, CUtensorMapDataType, cuuint32_t, void*,
    const cuuint64_t*, const cuuint64_t*, const cuuint32_t*, const cuuint32_t*,
    CUtensorMapInterleave, CUtensorMapSwizzle, CUtensorMapL2promotion,
    CUtensorMapFloatOOBfill);

extern "C" void kernel_launch(void* const* d_in, const int* in_sizes, int n_in,
                              void* d_out, int out_size)
{
    const int*   x     = (const int*)d_in[0];
    const float* emb   = (const float*)d_in[1];
    const float* Whh   = (const float*)d_in[2];
    const float* bhh   = (const float*)d_in[3];
    const float* Who   = (const float*)d_in[4];
    const float* bho   = (const float*)d_in[5];
    const float* gamma = (const float*)d_in[6];
    const float* beta  = (const float*)d_in[7];
    float* out = (float*)d_out;

    // Build TMA descriptors (host-only work; graph-capture safe)
    void* hsym = nullptr; cudaGetSymbolAddress(&hsym, g_h16);
    void* wsym = nullptr; cudaGetSymbolAddress(&wsym, g_Wh);
    PFN_tmap_enc enc = nullptr;
    cudaDriverEntryPointQueryResult qr;
    cudaGetDriverEntryPointByVersion("cuTensorMapEncodeTiled", (void**)&enc,
                                     12000, cudaEnableDefault, &qr);
    CUtensorMap mapH, mapW;
    {
        cuuint64_t dims[3] = {NHID, NB, 2};
        cuuint64_t strd[2] = {NHID * 2, (cuuint64_t)NB * NHID * 2};
        cuuint32_t box[3]  = {KCH, 128, 1};
        cuuint32_t es[3]   = {1, 1, 1};
        enc(&mapH, CU_TENSOR_MAP_DATA_TYPE_UINT16, 3, hsym, dims, strd, box, es,
            CU_TENSOR_MAP_INTERLEAVE_NONE, CU_TENSOR_MAP_SWIZZLE_128B,
            CU_TENSOR_MAP_L2_PROMOTION_L2_128B, CU_TENSOR_MAP_FLOAT_OOB_FILL_NONE);
    }
    {
        cuuint64_t dims[2] = {NHID, NHID};
        cuuint64_t strd[1] = {NHID * 2};
        cuuint32_t box[2]  = {KCH, 128};
        cuuint32_t es[2]   = {1, 1};
        enc(&mapW, CU_TENSOR_MAP_DATA_TYPE_UINT16, 2, wsym, dims, strd, box, es,
            CU_TENSOR_MAP_INTERLEAVE_NONE, CU_TENSOR_MAP_SWIZZLE_128B,
            CU_TENSOR_MAP_L2_PROMOTION_L2_128B, CU_TENSOR_MAP_FLOAT_OOB_FILL_NONE);
    }

    cudaFuncSetAttribute(k_persist, cudaFuncAttributeMaxDynamicSharedMemorySize,
                         SMEM_TOTAL);

    k_init<<<1024, 256>>>(Whh, emb, bhh);
    k_persist<<<NBLK, NTHR, SMEM_TOTAL>>>(mapH, mapW, x, Who, bho, gamma, beta, out);
}

// round 12
// speedup vs baseline: 7.5037x; 2.1847x over previous
#include <cuda_runtime.h>
#include <cuda.h>
#include <cuda_fp16.h>
#include <cstdint>

#define NB   2048
#define NT   512
#define NHID 1024
#define NVOC 31
#define EPS  1e-5f
#define NBLK 128
#define NTHR 512

#define KCH     64
#define NCHUNK  16
#define TILE16K 16384               // one 128x64 fp16 tile, 128B rows
#define STAGESZ 32768               // A tile + B tile
#define NSTAGE  4

// smem layout (dynamic)
#define OFF_MB   0                  // full[4]@0..31, empty[4]@32..63
#define OFF_XS   64                 // 128 ints -> 576
#define OFF_SS   576                // scale 1024f -> 4672
#define OFF_SH   4672               // shift -> 8768
#define OFF_GA   8768               // gamma -> 12864
#define OFF_BE   12864              // beta  -> 16960
#define OFF_SSH  16960              // sS as half2[512] -> 19008
#define OFF_CP   19008              // const partials 512f -> 21056
#define OFF_CV   21056              // const[32] -> 21184
#define OFF_RED  21248              // 32KB A-tile / C-partials -> 54016
#define OFF_BUF  54016
#define SMEM_TOTAL (OFF_BUF + 1024 + NSTAGE * STAGESZ)   // 186112

// ---- persistent device state ----
__device__ __align__(128) uint16_t g_h16[2][NB * NHID];  // h fp16 (TMA src)
__device__ __align__(128) uint16_t g_Wh[NHID * NHID];    // W_hh fp16 (TMA src)
__device__ __align__(128) uint16_t g_Who16[NVOC * NHID]; // W_ho fp16
__device__ __align__(16)  float    g_embW[NVOC * NHID];  // emb @ W^T + b_hh
__device__ __align__(16)  float    g_sum3[3][NHID];
__device__ __align__(16)  float    g_sumsq3[3][NHID];
__device__ unsigned g_count;

// ============================ PTX helpers ============================
__device__ __forceinline__ uint32_t smem_to_u32(const void* p) {
    uint32_t a;
    asm("{ .reg .u64 t; cvta.to.shared.u64 t, %1; cvt.u32.u64 %0, t; }"
        : "=r"(a) : "l"(p));
    return a;
}
#define MBARRIER_INIT(mb, cnt) \
    asm volatile("mbarrier.init.shared.b64 [%0], %1;" \
                 :: "r"((uint32_t)(mb)), "r"((uint32_t)(cnt)) : "memory")
#define MBARRIER_ARRIVE(mb) \
    asm volatile("mbarrier.arrive.shared.b64 _, [%0];" \
                 :: "r"((uint32_t)(mb)) : "memory")
#define MBARRIER_EXPECT_TX(mb, bytes) \
    asm volatile("mbarrier.arrive.expect_tx.shared.b64 _, [%0], %1;" \
                 :: "r"((uint32_t)(mb)), "r"((uint32_t)(bytes)) : "memory")
#define MBARRIER_WAIT_PARITY(mb, ph) do {                                   \
    uint32_t _m = (uint32_t)(mb); uint32_t _p = (uint32_t)(ph);             \
    asm volatile("{\n\t.reg .pred P1;\n\t"                                  \
        "WAIT_LOOP_%=:\n\t"                                                 \
        "mbarrier.try_wait.parity.acquire.cta.shared::cta.b64 P1, [%0], %1, 0x989680;\n\t" \
        "@P1 bra.uni WAIT_DONE_%=;\n\t"                                     \
        "bra.uni WAIT_LOOP_%=;\n\t"                                         \
        "WAIT_DONE_%=:\n\t}" :: "r"(_m), "r"(_p) : "memory");               \
} while (0)
#define FENCE_PROXY_ASYNC() asm volatile("fence.proxy.async;" ::: "memory")

__device__ __forceinline__ void ldsm4(uint32_t* r, uint32_t addr) {
    asm volatile("ldmatrix.sync.aligned.m8n8.x4.shared.b16 {%0,%1,%2,%3}, [%4];"
                 : "=r"(r[0]), "=r"(r[1]), "=r"(r[2]), "=r"(r[3]) : "r"(addr));
}
__device__ __forceinline__ void mma16816(float* c, const uint32_t* a,
                                         uint32_t b0, uint32_t b1) {
    asm volatile(
        "mma.sync.aligned.m16n8k16.row.col.f32.f16.f16.f32 "
        "{%0,%1,%2,%3}, {%4,%5,%6,%7}, {%8,%9}, {%0,%1,%2,%3};"
        : "+f"(c[0]), "+f"(c[1]), "+f"(c[2]), "+f"(c[3])
        : "r"(a[0]), "r"(a[1]), "r"(a[2]), "r"(a[3]), "r"(b0), "r"(b1));
}

// TMA issue for one 64-K chunk c of the step: A tile (h) + B tile (W)
__device__ __forceinline__ void issue_chunk(
    uint32_t sb, uint32_t bufabs,
    const CUtensorMap* mH, const CUtensorMap* mW,
    int curbuf, int m0, int n0, int c)
{
    const int s = c & 3;
    const uint32_t pe = ((uint32_t)(c >> 2) & 1u) ^ 1u;
    MBARRIER_WAIT_PARITY(sb + OFF_MB + 32 + s * 8, pe);
    MBARRIER_EXPECT_TX(sb + OFF_MB + s * 8, STAGESZ);
    const uint32_t dA = bufabs + s * STAGESZ;
    const int k0 = c * KCH;
    asm volatile(
        "cp.async.bulk.tensor.3d.shared::cta.global.tile.mbarrier::complete_tx::bytes "
        "[%0], [%1, {%2, %3, %4}], [%5];"
        :: "r"(dA), "l"(mH), "r"(k0), "r"(m0), "r"(curbuf),
           "r"(sb + OFF_MB + s * 8) : "memory");
    asm volatile(
        "cp.async.bulk.tensor.2d.shared::cta.global.tile.mbarrier::complete_tx::bytes "
        "[%0], [%1, {%2, %3}], [%4];"
        :: "r"(dA + TILE16K), "l"(mW), "r"(k0), "r"(n0),
           "r"(sb + OFF_MB + s * 8) : "memory");
}

// ---------------------------------------------------------------------------
// init: zero h[0]; W_hh,W_ho -> fp16; embW = emb@W^T + b_hh
// ---------------------------------------------------------------------------
__global__ void k_init(const float* __restrict__ W, const float* __restrict__ emb,
                       const float* __restrict__ bhh, const float* __restrict__ Who) {
    int gid = blockIdx.x * blockDim.x + threadIdx.x;
    int stride = gridDim.x * blockDim.x;
    uint32_t* zA = (uint32_t*)g_h16[0];
    for (int i = gid; i < NB * NHID / 2; i += stride) zA[i] = 0u;
    for (int i = gid; i < NHID * NHID; i += stride)
        g_Wh[i] = __half_as_ushort(__float2half_rn(W[i]));
    if (gid < NVOC * NHID) {
        g_Who16[gid] = __half_as_ushort(__float2half_rn(Who[gid]));
        int v = gid >> 10, n = gid & (NHID - 1);
        const float4* er = (const float4*)(emb + (size_t)v * NHID);
        const float4* wr = (const float4*)(W + (size_t)n * NHID);
        float s0 = 0.f, s1 = 0.f, s2 = 0.f, s3 = 0.f;
        for (int k = 0; k < NHID / 4; k++) {
            float4 e = er[k], w = wr[k];
            s0 = fmaf(e.x, w.x, s0); s1 = fmaf(e.y, w.y, s1);
            s2 = fmaf(e.z, w.z, s2); s3 = fmaf(e.w, w.w, s3);
        }
        g_embW[gid] = (s0 + s1) + (s2 + s3) + bhh[n];
    }
    if (gid < NHID) {
        for (int r = 0; r < 3; r++) { g_sum3[r][gid] = 0.f; g_sumsq3[r][gid] = 0.f; }
    }
    if (gid == 0) g_count = 0u;
}

// ---------------------------------------------------------------------------
// grid barrier (all 128 blocks resident) + async-proxy fence
// ---------------------------------------------------------------------------
__device__ __forceinline__ void gridbar(unsigned& epoch) {
    __syncthreads();
    epoch += NBLK;
    if (threadIdx.x == 0) {
        __threadfence();
        FENCE_PROXY_ASYNC();
        atomicAdd(&g_count, 1u);
        while (*(volatile unsigned*)&g_count < epoch) { }
        __threadfence();
    }
    __syncthreads();
}

// ---------------------------------------------------------------------------
// persistent kernel: 512 threads, 16 warps, warp tile 32x32
// ---------------------------------------------------------------------------
__global__ __launch_bounds__(NTHR, 1) void k_persist(
    const __grid_constant__ CUtensorMap mapH,
    const __grid_constant__ CUtensorMap mapW,
    const int* __restrict__ x,
    const float* __restrict__ bho,
    const float* __restrict__ gamma, const float* __restrict__ beta,
    float* __restrict__ out)
{
    extern __shared__ char smem[];
    const uint32_t sb = smem_to_u32(smem);
    const int tid = threadIdx.x;
    const int wid = tid >> 5;
    const int lane = tid & 31;
    const int b = blockIdx.x;
    const int n0 = (b & 7) * 128;
    const int m0 = (b >> 3) * 128;
    const int mw = wid >> 2;        // 0..3 : 32-row slice
    const int nw = wid & 3;         // 0..3 : 32-col slice

    int* xs = (int*)(smem + OFF_XS);
    float* sS = (float*)(smem + OFF_SS);
    float* sH = (float*)(smem + OFF_SH);
    float* sGa = (float*)(smem + OFF_GA);
    float* sBe = (float*)(smem + OFF_BE);
    uint32_t* sSh = (uint32_t*)(smem + OFF_SSH);
    float* cpart = (float*)(smem + OFF_CP);
    float* cv = (float*)(smem + OFF_CV);
    const uint32_t bufabs = (sb + OFF_BUF + 1023) & ~1023u;
    char* bufc = smem + (bufabs - sb);
    const uint32_t Ared = sb + OFF_RED;

    // ldmatrix per-lane constants (phase 1)
    const uint32_t raA0 = (uint32_t)(mw * 32 + (lane & 15)) * 128;
    const uint32_t raA1 = raA0 + 16 * 128;
    const uint32_t rxA = (uint32_t)(lane & 7);
    const uint32_t rbB0 = (uint32_t)(nw * 32 + (lane & 15)) * 128;
    const uint32_t rbB1 = rbB0 + 16 * 128;
    const uint32_t rxB = rxA;
    const int hl = lane >> 4;

    // mbarrier init + preload gamma/beta + xs(0)
    if (tid == 0) {
        for (int s = 0; s < NSTAGE; s++) {
            MBARRIER_INIT(sb + OFF_MB + s * 8, 1);        // full: tx-based
            MBARRIER_INIT(sb + OFF_MB + 32 + s * 8, 16);  // empty: 16 warps
        }
        FENCE_PROXY_ASYNC();
    }
    sGa[tid] = gamma[tid]; sGa[tid + 512] = gamma[tid + 512];
    sBe[tid] = beta[tid];  sBe[tid + 512] = beta[tid + 512];
    if (tid < 128) xs[tid] = x[(m0 + tid) * NT + 0];
    __syncthreads();

    if (tid == 0)
        for (int c = 0; c < 2; c++)
            issue_chunk(sb, bufabs, &mapH, &mapW, 0, m0, n0, c);

    unsigned epoch = 0;

    for (int t = 0; t < NT; t++) {
        const int cur = t & 1;
        uint16_t* hn = g_h16[cur ^ 1];
        const int sp = t % 3;

        // ============ phase 1: h @ W^T via fp16 mma, TMA-fed ============
        float acc[2][4][4];
#pragma unroll
        for (int mt = 0; mt < 2; mt++)
#pragma unroll
            for (int j = 0; j < 4; j++)
#pragma unroll
                for (int q = 0; q < 4; q++) acc[mt][j][q] = 0.f;

        for (int c = 0; c < NCHUNK; c++) {
            if (tid == 0 && c + 2 < NCHUNK)
                issue_chunk(sb, bufabs, &mapH, &mapW, cur, m0, n0, c + 2);
            const int s = c & 3;
            MBARRIER_WAIT_PARITY(sb + OFF_MB + s * 8, (uint32_t)((c >> 2) & 1));
            const uint32_t aB = bufabs + s * STAGESZ;
#pragma unroll
            for (int kt = 0; kt < 4; kt++) {
                const uint32_t segA = (uint32_t)(kt * 2 + hl);
                uint32_t a0[4], a1[4];
                {
                    uint32_t sa0 = aB + raA0 + ((segA ^ rxA) << 4);
                    uint32_t sa1 = aB + raA1 + ((segA ^ rxA) << 4);
                    ldsm4(a0, sa0); ldsm4(a1, sa1);
                }
                uint32_t bh[2][4];
                {
                    uint32_t sb0 = aB + TILE16K + rbB0 + ((segA ^ rxB) << 4);
                    uint32_t sb1 = aB + TILE16K + rbB1 + ((segA ^ rxB) << 4);
                    ldsm4(bh[0], sb0); ldsm4(bh[1], sb1);
                }
#pragma unroll
                for (int j = 0; j < 4; j++) {
                    const int g = j >> 1, o = j & 1;
                    mma16816(acc[0][j], a0, bh[g][o], bh[g][2 + o]);
                    mma16816(acc[1][j], a1, bh[g][o], bh[g][2 + o]);
                }
            }
            __syncwarp();
            if (lane == 0) MBARRIER_ARRIVE(sb + OFF_MB + 32 + s * 8);
        }

        // ============ epilogue: +embW[x], relu, fp16 store h, stats ========
        {
            const int cb = n0 + nw * 32 + (lane & 3) * 2;
            float csum[4][2], csq[4][2];
#pragma unroll
            for (int j = 0; j < 4; j++) {
                csum[j][0] = 0.f; csum[j][1] = 0.f;
                csq[j][0] = 0.f;  csq[j][1] = 0.f;
            }
#pragma unroll
            for (int mt = 0; mt < 2; mt++) {
#pragma unroll
                for (int rr = 0; rr < 2; rr++) {
                    const int lrow = mw * 32 + mt * 16 + rr * 8 + (lane >> 2);
                    const int row = m0 + lrow;
                    const float* ew = g_embW + (size_t)xs[lrow] * NHID;
                    uint16_t* dH = hn + (size_t)row * NHID;
#pragma unroll
                    for (int j = 0; j < 4; j++) {
                        const int col = cb + j * 8;
                        float2 e = *(const float2*)(ew + col);
                        float v0 = fmaxf(acc[mt][j][rr * 2 + 0] + e.x, 0.f);
                        float v1 = fmaxf(acc[mt][j][rr * 2 + 1] + e.y, 0.f);
                        __half2 hv = __floats2half2_rn(v0, v1);
                        *(uint32_t*)(dH + col) = *(uint32_t*)&hv;
                        csum[j][0] += v0; csum[j][1] += v1;
                        csq[j][0] = fmaf(v0, v0, csq[j][0]);
                        csq[j][1] = fmaf(v1, v1, csq[j][1]);
                    }
                }
            }
#pragma unroll
            for (int j = 0; j < 4; j++) {
                float s0 = csum[j][0], s1 = csum[j][1];
                float q0 = csq[j][0], q1 = csq[j][1];
                s0 += __shfl_down_sync(~0u, s0, 16);
                s1 += __shfl_down_sync(~0u, s1, 16);
                q0 += __shfl_down_sync(~0u, q0, 16);
                q1 += __shfl_down_sync(~0u, q1, 16);
                s0 += __shfl_down_sync(~0u, s0, 8);
                s1 += __shfl_down_sync(~0u, s1, 8);
                q0 += __shfl_down_sync(~0u, q0, 8);
                q1 += __shfl_down_sync(~0u, q1, 8);
                s0 += __shfl_down_sync(~0u, s0, 4);
                s1 += __shfl_down_sync(~0u, s1, 4);
                q0 += __shfl_down_sync(~0u, q0, 4);
                q1 += __shfl_down_sync(~0u, q1, 4);
                if (lane < 4) {
                    const int col = n0 + nw * 32 + j * 8 + lane * 2;
                    atomicAdd(&g_sum3[sp][col], s0);
                    atomicAdd(&g_sum3[sp][col + 1], s1);
                    atomicAdd(&g_sumsq3[sp][col], q0);
                    atomicAdd(&g_sumsq3[sp][col + 1], q1);
                }
            }
        }

        gridbar(epoch);

        // prefetch chunks 0,1 of step t+1 (stages 0,1 — B' uses stages 2,3)
        if (t < NT - 1 && tid == 0)
            for (int c = 0; c < 2; c++)
                issue_chunk(sb, bufabs, &mapH, &mapW, cur ^ 1, m0, n0, c);

        // ======== post-bar: zero stale stats; scale/shift; xs(t+1) =========
        {
            const int st = (t + 2) % 3;   // == (t-1) mod 3
            if (tid < 8) g_sum3[st][b * 8 + tid] = 0.f;
            else if (tid < 16) g_sumsq3[st][b * 8 + tid - 8] = 0.f;
#pragma unroll
            for (int u = 0; u < 2; u++) {
                const int c = tid + u * NTHR;
                float mu = g_sum3[sp][c] * (1.f / NB);
                float var = g_sumsq3[sp][c] * (1.f / NB) - mu * mu;
                float rs = rsqrtf(var + EPS);
                float sc = rs * sGa[c];
                sS[c] = sc;
                sH[c] = sBe[c] - mu * sc;
            }
            if (t < NT - 1 && tid < 128) xs[tid] = x[(m0 + tid) * NT + t + 1];
        }
        __syncthreads();

        // ============ phase 3: output GEMM via MMA, BN folded ============
        {
            const int om0 = b * 16;
            const uint32_t Bp = bufabs + 2 * STAGESZ;    // B' in stages 2,3
            char* Bpc = bufc + 2 * STAGESZ;

            // sSh pack; A-tile stage; const partials
            {
                __half2 p = __floats2half2_rn(sS[2 * tid], sS[2 * tid + 1]);
                sSh[tid] = *(uint32_t*)&p;
#pragma unroll
                for (int u = 0; u < 4; u++) {
                    int idx = tid + u * 512;
                    int row = idx >> 7, seg = idx & 127;
                    uint4 d = *(const uint4*)(hn + (size_t)(om0 + row) * NHID + seg * 8);
                    *(uint4*)(smem + OFF_RED + row * 2048 +
                              ((seg ^ (row & 7)) << 4)) = d;
                }
                const int v = tid >> 4, s0i = tid & 15;
                float cp = 0.f;
                if (v < NVOC) {
#pragma unroll
                    for (int i = 0; i < 8; i++) {
                        int seg = s0i + i * 16;
                        uint4 wq = *(const uint4*)((const char*)g_Who16 +
                                                   v * 2048 + seg * 16);
                        const float* sh = sH + seg * 8;
                        const __half2* hp = (const __half2*)&wq;
#pragma unroll
                        for (int q = 0; q < 4; q++) {
                            float2 f = __half22float2(hp[q]);
                            cp = fmaf(sh[2 * q], f.x, cp);
                            cp = fmaf(sh[2 * q + 1], f.y, cp);
                        }
                    }
                }
                cpart[tid] = cp;
            }
            __syncthreads();

            // B' build (stages 2,3) + const reduce
            {
                const int v = tid >> 4, s0i = tid & 15;
#pragma unroll
                for (int i = 0; i < 8; i++) {
                    int seg = s0i + i * 16;
                    uint4 wq = make_uint4(0u, 0u, 0u, 0u);
                    if (v < NVOC)
                        wq = *(const uint4*)((const char*)g_Who16 + v * 2048 + seg * 16);
                    uint4 sq = *(const uint4*)((const char*)sSh + seg * 16);
                    uint4 r;
                    {
                        __half2* wp = (__half2*)&wq;
                        __half2* sp2 = (__half2*)&sq;
                        __half2* rp = (__half2*)&r;
#pragma unroll
                        for (int q = 0; q < 4; q++) rp[q] = __hmul2(wp[q], sp2[q]);
                    }
                    *(uint4*)(Bpc + v * 2048 + ((seg ^ (v & 7)) << 4)) = r;
                }
                if (tid < 32) {
                    float s = 0.f;
#pragma unroll
                    for (int i = 0; i < 16; i++) s += cpart[tid * 16 + i];
                    cv[tid] = (tid < NVOC) ? s + bho[tid] : 0.f;
                }
            }
            __syncthreads();

            // MMA: warp wid covers k-slice [wid*64, wid*64+64)
            float pc[4][4];
#pragma unroll
            for (int j = 0; j < 4; j++)
#pragma unroll
                for (int q = 0; q < 4; q++) pc[j][q] = 0.f;
            {
                const int ks0 = wid * 64;
                const int arow = lane & 15;
                const int nrow0 = lane & 15;
                const int nrow1 = 16 + (lane & 15);
#pragma unroll
                for (int kt = 0; kt < 4; kt++) {
                    const int segk = ((ks0 + kt * 16) >> 3) + (lane >> 4);
                    uint32_t a[4];
                    ldsm4(a, Ared + arow * 2048 + ((segk ^ (arow & 7)) << 4));
                    uint32_t b0[4], b1[4];
                    ldsm4(b0, Bp + nrow0 * 2048 + ((segk ^ (nrow0 & 7)) << 4));
                    ldsm4(b1, Bp + nrow1 * 2048 + ((segk ^ (nrow1 & 7)) << 4));
#pragma unroll
                    for (int j = 0; j < 4; j++) {
                        const int o = j & 1;
                        if (j < 2) mma16816(pc[j], a, b0[o], b0[2 + o]);
                        else       mma16816(pc[j], a, b1[o], b1[2 + o]);
                    }
                }
            }
            __syncthreads();   // all A reads done; reuse region for partials

            // store partial C (16x32 per warp), bank-staggered
            {
#pragma unroll
                for (int j = 0; j < 4; j++) {
                    const int r0 = lane >> 2;
                    const int colb = j * 8 + (lane & 3) * 2;
                    float2 lo = make_float2(pc[j][0], pc[j][1]);
                    float2 hi = make_float2(pc[j][2], pc[j][3]);
                    *(float2*)(smem + OFF_RED + wid * 2048 + r0 * 128 +
                               ((colb * 4 + r0 * 32) & 127)) = lo;
                    const int r1 = r0 + 8;
                    *(float2*)(smem + OFF_RED + wid * 2048 + r1 * 128 +
                               ((colb * 4 + r1 * 32) & 127)) = hi;
                }
            }
            __syncthreads();

            // reduce 16 partials, add const, write out
            {
                const int row = tid >> 5, col = tid & 31;
                float s = 0.f;
#pragma unroll
                for (int w = 0; w < 16; w++)
                    s += *(const float*)(smem + OFF_RED + w * 2048 + row * 128 +
                                         ((col * 4 + row * 32) & 127));
                if (col < NVOC) {
                    size_t orow = om0 + row;
                    out[orow * (size_t)(NT * NVOC) + (size_t)t * NVOC + col] =
                        s + cv[col];
                }
            }
            __syncthreads();   // partials dead before next epilogue reuses region
        }
    }
}

// ---------------------------------------------------------------------------
typedef CUresult (CUDAAPI *PFN_tmap_enc)(
    CUtensorMap*, CUtensorMapDataType, cuuint32_t, void*,
    const cuuint64_t*, const cuuint64_t*, const cuuint32_t*, const cuuint32_t*,
    CUtensorMapInterleave, CUtensorMapSwizzle, CUtensorMapL2promotion,
    CUtensorMapFloatOOBfill);

extern "C" void kernel_launch(void* const* d_in, const int* in_sizes, int n_in,
                              void* d_out, int out_size)
{
    const int*   x     = (const int*)d_in[0];
    const float* emb   = (const float*)d_in[1];
    const float* Whh   = (const float*)d_in[2];
    const float* bhh   = (const float*)d_in[3];
    const float* Who   = (const float*)d_in[4];
    const float* bho   = (const float*)d_in[5];
    const float* gamma = (const float*)d_in[6];
    const float* beta  = (const float*)d_in[7];
    float* out = (float*)d_out;

    // Build TMA descriptors (host-only; graph-capture safe)
    void* hsym = nullptr; cudaGetSymbolAddress(&hsym, g_h16);
    void* wsym = nullptr; cudaGetSymbolAddress(&wsym, g_Wh);
    PFN_tmap_enc enc = nullptr;
    cudaDriverEntryPointQueryResult qr;
    cudaGetDriverEntryPointByVersion("cuTensorMapEncodeTiled", (void**)&enc,
                                     12000, cudaEnableDefault, &qr);
    CUtensorMap mapH, mapW;
    {
        cuuint64_t dims[3] = {NHID, NB, 2};
        cuuint64_t strd[2] = {NHID * 2, (cuuint64_t)NB * NHID * 2};
        cuuint32_t box[3]  = {KCH, 128, 1};
        cuuint32_t es[3]   = {1, 1, 1};
        enc(&mapH, CU_TENSOR_MAP_DATA_TYPE_UINT16, 3, hsym, dims, strd, box, es,
            CU_TENSOR_MAP_INTERLEAVE_NONE, CU_TENSOR_MAP_SWIZZLE_128B,
            CU_TENSOR_MAP_L2_PROMOTION_L2_128B, CU_TENSOR_MAP_FLOAT_OOB_FILL_NONE);
    }
    {
        cuuint64_t dims[2] = {NHID, NHID};
        cuuint64_t strd[1] = {NHID * 2};
        cuuint32_t box[2]  = {KCH, 128};
        cuuint32_t es[2]   = {1, 1};
        enc(&mapW, CU_TENSOR_MAP_DATA_TYPE_UINT16, 2, wsym, dims, strd, box, es,
            CU_TENSOR_MAP_INTERLEAVE_NONE, CU_TENSOR_MAP_SWIZZLE_128B,
            CU_TENSOR_MAP_L2_PROMOTION_L2_128B, CU_TENSOR_MAP_FLOAT_OOB_FILL_NONE);
    }

    cudaFuncSetAttribute(k_persist, cudaFuncAttributeMaxDynamicSharedMemorySize,
                         SMEM_TOTAL);

    k_init<<<1024, 256>>>(Whh, emb, bhh, Who);
    k_persist<<<NBLK, NTHR, SMEM_TOTAL>>>(mapH, mapW, x, bho, gamma, beta, out);
}

// round 13
// speedup vs baseline: 8.3301x; 1.1101x over previous
#include <cuda_runtime.h>
#include <cuda.h>
#include <cuda_fp16.h>
#include <cstdint>

#define NB   2048
#define NT   512
#define NHID 1024
#define NVOC 31
#define EPS  1e-5f
#define NBLK 128
#define NTHR 512

#define KCH     64
#define NCHUNK  16
#define TILE16K 16384               // one 128x64 fp16 tile, 128B rows
#define STAGESZ 32768               // A tile + B tile
#define NSTAGE  3

// smem layout (dynamic)
#define OFF_MB    0                 // full[3]@0,8,16 ; empty[3]@24,32,40
#define OFF_XS    64                // 128 ints -> 576
#define OFF_S16   576               // sS half2[512] -> 2624
#define OFF_H16S  2624              // sH half2[512] -> 4672
#define OFF_GA    4672              // gamma -> 8768
#define OFF_BE    8768              // beta  -> 12864
#define OFF_CV    12864             // bho[32] -> 12992
#define OFF_RED   13056             // 32KB A-norm / C-partials -> 45824
#define OFF_WHO   45824             // 64KB Who16 swizzled (32 x 2048B) -> 111360
#define OFF_BUF   111360
#define SMEM_TOTAL (OFF_BUF + 1024 + NSTAGE * STAGESZ)   // 210688

// ---- persistent device state ----
__device__ __align__(128) uint16_t g_h16[2][NB * NHID];  // h fp16 (TMA src)
__device__ __align__(128) uint16_t g_Wh[NHID * NHID];    // W_hh fp16 (TMA src)
__device__ __align__(128) uint16_t g_Who16[NVOC * NHID]; // W_ho fp16
__device__ __align__(16)  float    g_embW[NVOC * NHID];  // emb @ W^T + b_hh
__device__ __align__(16)  float    g_sum3[3][NHID];
__device__ __align__(16)  float    g_sumsq3[3][NHID];
__device__ __align__(128) unsigned g_cnt8[8 * 32];       // distributed barrier

// ============================ PTX helpers ============================
__device__ __forceinline__ uint32_t smem_to_u32(const void* p) {
    uint32_t a;
    asm("{ .reg .u64 t; cvta.to.shared.u64 t, %1; cvt.u32.u64 %0, t; }"
        : "=r"(a) : "l"(p));
    return a;
}
#define MBARRIER_INIT(mb, cnt) \
    asm volatile("mbarrier.init.shared.b64 [%0], %1;" \
                 :: "r"((uint32_t)(mb)), "r"((uint32_t)(cnt)) : "memory")
#define MBARRIER_ARRIVE(mb) \
    asm volatile("mbarrier.arrive.shared.b64 _, [%0];" \
                 :: "r"((uint32_t)(mb)) : "memory")
#define MBARRIER_EXPECT_TX(mb, bytes) \
    asm volatile("mbarrier.arrive.expect_tx.shared.b64 _, [%0], %1;" \
                 :: "r"((uint32_t)(mb)), "r"((uint32_t)(bytes)) : "memory")
#define MBARRIER_WAIT_PARITY(mb, ph) do {                                   \
    uint32_t _m = (uint32_t)(mb); uint32_t _p = (uint32_t)(ph);             \
    asm volatile("{\n\t.reg .pred P1;\n\t"                                  \
        "WAIT_LOOP_%=:\n\t"                                                 \
        "mbarrier.try_wait.parity.acquire.cta.shared::cta.b64 P1, [%0], %1, 0x989680;\n\t" \
        "@P1 bra.uni WAIT_DONE_%=;\n\t"                                     \
        "bra.uni WAIT_LOOP_%=;\n\t"                                         \
        "WAIT_DONE_%=:\n\t}" :: "r"(_m), "r"(_p) : "memory");               \
} while (0)
#define FENCE_PROXY_ASYNC() asm volatile("fence.proxy.async;" ::: "memory")

__device__ __forceinline__ void ldsm4(uint32_t* r, uint32_t addr) {
    asm volatile("ldmatrix.sync.aligned.m8n8.x4.shared.b16 {%0,%1,%2,%3}, [%4];"
                 : "=r"(r[0]), "=r"(r[1]), "=r"(r[2]), "=r"(r[3]) : "r"(addr));
}
__device__ __forceinline__ void mma16816(float* c, const uint32_t* a,
                                         uint32_t b0, uint32_t b1) {
    asm volatile(
        "mma.sync.aligned.m16n8k16.row.col.f32.f16.f16.f32 "
        "{%0,%1,%2,%3}, {%4,%5,%6,%7}, {%8,%9}, {%0,%1,%2,%3};"
        : "+f"(c[0]), "+f"(c[1]), "+f"(c[2]), "+f"(c[3])
        : "r"(a[0]), "r"(a[1]), "r"(a[2]), "r"(a[3]), "r"(b0), "r"(b1));
}

// TMA issue for global chunk G = t*16 + c : stage G%3, h-buffer (G>>4)&1
__device__ __forceinline__ void issue_chunk(
    uint32_t sb, uint32_t bufabs,
    const CUtensorMap* mH, const CUtensorMap* mW,
    int m0, int n0, unsigned G)
{
    const unsigned s = G % 3u;
    const unsigned u = G / 3u;
    MBARRIER_WAIT_PARITY(sb + OFF_MB + 24 + s * 8, (u & 1u) ^ 1u);
    MBARRIER_EXPECT_TX(sb + OFF_MB + s * 8, STAGESZ);
    const uint32_t dA = bufabs + s * STAGESZ;
    const int k0 = (int)(G & 15u) * KCH;
    const int zb = (int)((G >> 4) & 1u);
    asm volatile(
        "cp.async.bulk.tensor.3d.shared::cta.global.tile.mbarrier::complete_tx::bytes "
        "[%0], [%1, {%2, %3, %4}], [%5];"
        :: "r"(dA), "l"(mH), "r"(k0), "r"(m0), "r"(zb),
           "r"(sb + OFF_MB + s * 8) : "memory");
    asm volatile(
        "cp.async.bulk.tensor.2d.shared::cta.global.tile.mbarrier::complete_tx::bytes "
        "[%0], [%1, {%2, %3}], [%4];"
        :: "r"(dA + TILE16K), "l"(mW), "r"(k0), "r"(n0),
           "r"(sb + OFF_MB + s * 8) : "memory");
}

// ---------------------------------------------------------------------------
// init: zero h[0] + counters; W_hh,W_ho -> fp16; embW = emb@W^T + b_hh
// ---------------------------------------------------------------------------
__global__ void k_init(const float* __restrict__ W, const float* __restrict__ emb,
                       const float* __restrict__ bhh, const float* __restrict__ Who) {
    int gid = blockIdx.x * blockDim.x + threadIdx.x;
    int stride = gridDim.x * blockDim.x;
    uint32_t* zA = (uint32_t*)g_h16[0];
    for (int i = gid; i < NB * NHID / 2; i += stride) zA[i] = 0u;
    for (int i = gid; i < NHID * NHID; i += stride)
        g_Wh[i] = __half_as_ushort(__float2half_rn(W[i]));
    if (gid < NVOC * NHID) {
        g_Who16[gid] = __half_as_ushort(__float2half_rn(Who[gid]));
        int v = gid >> 10, n = gid & (NHID - 1);
        const float4* er = (const float4*)(emb + (size_t)v * NHID);
        const float4* wr = (const float4*)(W + (size_t)n * NHID);
        float s0 = 0.f, s1 = 0.f, s2 = 0.f, s3 = 0.f;
        for (int k = 0; k < NHID / 4; k++) {
            float4 e = er[k], w = wr[k];
            s0 = fmaf(e.x, w.x, s0); s1 = fmaf(e.y, w.y, s1);
            s2 = fmaf(e.z, w.z, s2); s3 = fmaf(e.w, w.w, s3);
        }
        g_embW[gid] = (s0 + s1) + (s2 + s3) + bhh[n];
    }
    if (gid < NHID) {
        for (int r = 0; r < 3; r++) { g_sum3[r][gid] = 0.f; g_sumsq3[r][gid] = 0.f; }
    }
    if (gid < 8 * 32) g_cnt8[gid] = 0u;
}

// ---------------------------------------------------------------------------
// distributed grid barrier: 8 padded counters, 16 arrivals each
// ---------------------------------------------------------------------------
__device__ __forceinline__ void gridbar(unsigned& target, int b, int tid) {
    __syncthreads();
    target += 16;
    if (tid == 0) {
        __threadfence();
        FENCE_PROXY_ASYNC();
        atomicAdd(&g_cnt8[(b & 7) * 32], 1u);
    }
    if (tid < 8) {
        while (*(volatile unsigned*)&g_cnt8[tid * 32] < target) { }
        __threadfence();
    }
    __syncthreads();
}

// ---------------------------------------------------------------------------
// persistent kernel: 512 threads, 16 warps, warp tile 32x32
// ---------------------------------------------------------------------------
__global__ __launch_bounds__(NTHR, 1) void k_persist(
    const __grid_constant__ CUtensorMap mapH,
    const __grid_constant__ CUtensorMap mapW,
    const int* __restrict__ x,
    const float* __restrict__ bho,
    const float* __restrict__ gamma, const float* __restrict__ beta,
    float* __restrict__ out)
{
    extern __shared__ char smem[];
    const uint32_t sb = smem_to_u32(smem);
    const int tid = threadIdx.x;
    const int wid = tid >> 5;
    const int lane = tid & 31;
    const int b = blockIdx.x;
    const int n0 = (b & 7) * 128;
    const int m0 = (b >> 3) * 128;
    const int mw = wid >> 2;        // 0..3 : 32-row slice
    const int nw = wid & 3;         // 0..3 : 32-col slice

    int* xs = (int*)(smem + OFF_XS);
    float* sGa = (float*)(smem + OFF_GA);
    float* sBe = (float*)(smem + OFF_BE);
    float* cv = (float*)(smem + OFF_CV);
    const uint32_t bufabs = (sb + OFF_BUF + 1023) & ~1023u;
    const uint32_t Ared = sb + OFF_RED;
    const uint32_t Bwho = sb + OFF_WHO;

    // ldmatrix per-lane constants (phase 1)
    const uint32_t raA0 = (uint32_t)(mw * 32 + (lane & 15)) * 128;
    const uint32_t raA1 = raA0 + 16 * 128;
    const uint32_t rxA = (uint32_t)(lane & 7);
    const uint32_t rbB0 = (uint32_t)(nw * 32 + (lane & 15)) * 128;
    const uint32_t rbB1 = rbB0 + 16 * 128;
    const uint32_t rxB = rxA;
    const int hl = lane >> 4;

    // mbarrier init + preload gamma/beta/bho + xs(0)
    if (tid == 0) {
        for (int s = 0; s < NSTAGE; s++) {
            MBARRIER_INIT(sb + OFF_MB + s * 8, 1);        // full: tx-based
            MBARRIER_INIT(sb + OFF_MB + 24 + s * 8, 16);  // empty: 16 warps
        }
        FENCE_PROXY_ASYNC();
    }
    sGa[tid] = gamma[tid]; sGa[tid + 512] = gamma[tid + 512];
    sBe[tid] = beta[tid];  sBe[tid + 512] = beta[tid + 512];
    if (tid < 32) cv[tid] = (tid < NVOC) ? bho[tid] : 0.f;
    if (tid < 128) xs[tid] = x[(m0 + tid) * NT + 0];

    // build swizzled Who16 in smem ONCE (row 31 zero)
    {
        const int v = tid >> 4, s0i = tid & 15;
#pragma unroll
        for (int i = 0; i < 8; i++) {
            int seg = s0i + i * 16;
            uint4 wq = make_uint4(0u, 0u, 0u, 0u);
            if (v < NVOC)
                wq = *(const uint4*)((const char*)g_Who16 + v * 2048 + seg * 16);
            *(uint4*)(smem + OFF_WHO + v * 2048 + ((seg ^ (v & 7)) << 4)) = wq;
        }
    }
    __syncthreads();

    if (tid == 0) {
        issue_chunk(sb, bufabs, &mapH, &mapW, m0, n0, 0u);
        issue_chunk(sb, bufabs, &mapH, &mapW, m0, n0, 1u);
    }

    unsigned target = 0;

    for (int t = 0; t < NT; t++) {
        const int cur = t & 1;
        uint16_t* hn = g_h16[cur ^ 1];
        const int sp = t % 3;
        const unsigned Gbase = (unsigned)t * 16u;

        // ============ phase 1: h @ W^T via fp16 mma, TMA-fed ============
        float acc[2][4][4];
#pragma unroll
        for (int mt = 0; mt < 2; mt++)
#pragma unroll
            for (int j = 0; j < 4; j++)
#pragma unroll
                for (int q = 0; q < 4; q++) acc[mt][j][q] = 0.f;

        for (int c = 0; c < NCHUNK; c++) {
            if (tid == 0 && c + 2 < NCHUNK)
                issue_chunk(sb, bufabs, &mapH, &mapW, m0, n0, Gbase + c + 2);
            const unsigned G = Gbase + c;
            const unsigned s = G % 3u;
            MBARRIER_WAIT_PARITY(sb + OFF_MB + s * 8, (G / 3u) & 1u);
            const uint32_t aB = bufabs + s * STAGESZ;
#pragma unroll
            for (int kt = 0; kt < 4; kt++) {
                const uint32_t segA = (uint32_t)(kt * 2 + hl);
                uint32_t a0[4], a1[4];
                {
                    uint32_t sa0 = aB + raA0 + ((segA ^ rxA) << 4);
                    uint32_t sa1 = aB + raA1 + ((segA ^ rxA) << 4);
                    ldsm4(a0, sa0); ldsm4(a1, sa1);
                }
                uint32_t bh[2][4];
                {
                    uint32_t sb0 = aB + TILE16K + rbB0 + ((segA ^ rxB) << 4);
                    uint32_t sb1 = aB + TILE16K + rbB1 + ((segA ^ rxB) << 4);
                    ldsm4(bh[0], sb0); ldsm4(bh[1], sb1);
                }
#pragma unroll
                for (int j = 0; j < 4; j++) {
                    const int g = j >> 1, o = j & 1;
                    mma16816(acc[0][j], a0, bh[g][o], bh[g][2 + o]);
                    mma16816(acc[1][j], a1, bh[g][o], bh[g][2 + o]);
                }
            }
            __syncwarp();
            if (lane == 0) MBARRIER_ARRIVE(sb + OFF_MB + 24 + s * 8);
        }

        // ============ epilogue: +embW[x], relu, fp16 store h, stats ========
        {
            const int cb = n0 + nw * 32 + (lane & 3) * 2;
            float csum[4][2], csq[4][2];
#pragma unroll
            for (int j = 0; j < 4; j++) {
                csum[j][0] = 0.f; csum[j][1] = 0.f;
                csq[j][0] = 0.f;  csq[j][1] = 0.f;
            }
#pragma unroll
            for (int mt = 0; mt < 2; mt++) {
#pragma unroll
                for (int rr = 0; rr < 2; rr++) {
                    const int lrow = mw * 32 + mt * 16 + rr * 8 + (lane >> 2);
                    const int row = m0 + lrow;
                    const float* ew = g_embW + (size_t)xs[lrow] * NHID;
                    uint16_t* dH = hn + (size_t)row * NHID;
#pragma unroll
                    for (int j = 0; j < 4; j++) {
                        const int col = cb + j * 8;
                        float2 e = *(const float2*)(ew + col);
                        float v0 = fmaxf(acc[mt][j][rr * 2 + 0] + e.x, 0.f);
                        float v1 = fmaxf(acc[mt][j][rr * 2 + 1] + e.y, 0.f);
                        __half2 hv = __floats2half2_rn(v0, v1);
                        *(uint32_t*)(dH + col) = *(uint32_t*)&hv;
                        csum[j][0] += v0; csum[j][1] += v1;
                        csq[j][0] = fmaf(v0, v0, csq[j][0]);
                        csq[j][1] = fmaf(v1, v1, csq[j][1]);
                    }
                }
            }
#pragma unroll
            for (int j = 0; j < 4; j++) {
                float s0 = csum[j][0], s1 = csum[j][1];
                float q0 = csq[j][0], q1 = csq[j][1];
                s0 += __shfl_down_sync(~0u, s0, 16);
                s1 += __shfl_down_sync(~0u, s1, 16);
                q0 += __shfl_down_sync(~0u, q0, 16);
                q1 += __shfl_down_sync(~0u, q1, 16);
                s0 += __shfl_down_sync(~0u, s0, 8);
                s1 += __shfl_down_sync(~0u, s1, 8);
                q0 += __shfl_down_sync(~0u, q0, 8);
                q1 += __shfl_down_sync(~0u, q1, 8);
                s0 += __shfl_down_sync(~0u, s0, 4);
                s1 += __shfl_down_sync(~0u, s1, 4);
                q0 += __shfl_down_sync(~0u, q0, 4);
                q1 += __shfl_down_sync(~0u, q1, 4);
                if (lane < 4) {
                    const int col = n0 + nw * 32 + j * 8 + lane * 2;
                    atomicAdd(&g_sum3[sp][col], s0);
                    atomicAdd(&g_sum3[sp][col + 1], s1);
                    atomicAdd(&g_sumsq3[sp][col], q0);
                    atomicAdd(&g_sumsq3[sp][col + 1], q1);
                }
            }
        }

        gridbar(target, b, tid);

        // prefetch chunks 0,1 of step t+1 (h(t+1) now globally visible)
        if (t < NT - 1 && tid == 0) {
            issue_chunk(sb, bufabs, &mapH, &mapW, m0, n0, Gbase + 16u);
            issue_chunk(sb, bufabs, &mapH, &mapW, m0, n0, Gbase + 17u);
        }

        // ======== post-bar: zero stale stats; pack fp16 scale/shift ========
        {
            const int st = (t + 2) % 3;   // == (t-1) mod 3
            if (tid < 8) g_sum3[st][b * 8 + tid] = 0.f;
            else if (tid < 16) g_sumsq3[st][b * 8 + tid - 8] = 0.f;
            const int c0 = tid * 2;
            float mu0 = g_sum3[sp][c0] * (1.f / NB);
            float mu1 = g_sum3[sp][c0 + 1] * (1.f / NB);
            float vr0 = g_sumsq3[sp][c0] * (1.f / NB) - mu0 * mu0;
            float vr1 = g_sumsq3[sp][c0 + 1] * (1.f / NB) - mu1 * mu1;
            float sc0 = rsqrtf(vr0 + EPS) * sGa[c0];
            float sc1 = rsqrtf(vr1 + EPS) * sGa[c0 + 1];
            float sh0 = sBe[c0] - mu0 * sc0;
            float sh1 = sBe[c0 + 1] - mu1 * sc1;
            __half2 ps = __floats2half2_rn(sc0, sc1);
            __half2 ph = __floats2half2_rn(sh0, sh1);
            ((uint32_t*)(smem + OFF_S16))[tid] = *(uint32_t*)&ps;
            ((uint32_t*)(smem + OFF_H16S))[tid] = *(uint32_t*)&ph;
            if (t < NT - 1 && tid < 128) xs[tid] = x[(m0 + tid) * NT + t + 1];
        }
        __syncthreads();

        // ============ phase 3: out = norm(h) @ Who16^T + bho (MMA) =========
        {
            const int om0 = b * 16;
            // stage normalized A tile in fp16 (hfma2 folds BN)
#pragma unroll
            for (int u = 0; u < 4; u++) {
                int idx = tid + u * 512;
                int row = idx >> 7, seg = idx & 127;
                uint4 d = *(const uint4*)(hn + (size_t)(om0 + row) * NHID + seg * 8);
                uint4 sv = ((const uint4*)(smem + OFF_S16))[seg];
                uint4 hv = ((const uint4*)(smem + OFF_H16S))[seg];
                uint4 r;
                {
                    __half2* dp = (__half2*)&d;
                    __half2* sp2 = (__half2*)&sv;
                    __half2* hp = (__half2*)&hv;
                    __half2* rp = (__half2*)&r;
#pragma unroll
                    for (int q = 0; q < 4; q++) rp[q] = __hfma2(dp[q], sp2[q], hp[q]);
                }
                *(uint4*)(smem + OFF_RED + row * 2048 + ((seg ^ (row & 7)) << 4)) = r;
            }
            __syncthreads();

            // MMA: warp wid covers k-slice [wid*64, wid*64+64)
            float pc[4][4];
#pragma unroll
            for (int j = 0; j < 4; j++)
#pragma unroll
                for (int q = 0; q < 4; q++) pc[j][q] = 0.f;
            {
                const int ks0 = wid * 64;
                const int arow = lane & 15;
                const int nrow0 = lane & 15;
                const int nrow1 = 16 + (lane & 15);
#pragma unroll
                for (int kt = 0; kt < 4; kt++) {
                    const int segk = ((ks0 + kt * 16) >> 3) + (lane >> 4);
                    uint32_t a[4];
                    ldsm4(a, Ared + arow * 2048 + ((segk ^ (arow & 7)) << 4));
                    uint32_t b0[4], b1[4];
                    ldsm4(b0, Bwho + nrow0 * 2048 + ((segk ^ (nrow0 & 7)) << 4));
                    ldsm4(b1, Bwho + nrow1 * 2048 + ((segk ^ (nrow1 & 7)) << 4));
#pragma unroll
                    for (int j = 0; j < 4; j++) {
                        const int o = j & 1;
                        if (j < 2) mma16816(pc[j], a, b0[o], b0[2 + o]);
                        else       mma16816(pc[j], a, b1[o], b1[2 + o]);
                    }
                }
            }
            __syncthreads();   // A reads done; reuse region for partials

            // store partial C (16x32 per warp), bank-staggered
#pragma unroll
            for (int j = 0; j < 4; j++) {
                const int r0 = lane >> 2;
                const int colb = j * 8 + (lane & 3) * 2;
                float2 lo = make_float2(pc[j][0], pc[j][1]);
                float2 hi = make_float2(pc[j][2], pc[j][3]);
                *(float2*)(smem + OFF_RED + wid * 2048 + r0 * 128 +
                           ((colb * 4 + r0 * 32) & 127)) = lo;
                const int r1 = r0 + 8;
                *(float2*)(smem + OFF_RED + wid * 2048 + r1 * 128 +
                           ((colb * 4 + r1 * 32) & 127)) = hi;
            }
            __syncthreads();

            // reduce 16 partials, add bho, write out
            {
                const int row = tid >> 5, col = tid & 31;
                float s = 0.f;
#pragma unroll
                for (int w = 0; w < 16; w++)
                    s += *(const float*)(smem + OFF_RED + w * 2048 + row * 128 +
                                         ((col * 4 + row * 32) & 127));
                if (col < NVOC) {
                    size_t orow = om0 + row;
                    out[orow * (size_t)(NT * NVOC) + (size_t)t * NVOC + col] =
                        s + cv[col];
                }
            }
            // next write to OFF_RED is next step's phase 3 (after gridbar)
        }
    }
}

// ---------------------------------------------------------------------------
typedef CUresult (CUDAAPI *PFN_tmap_enc)(
    CUtensorMap*, CUtensorMapDataType, cuuint32_t, void*,
    const cuuint64_t*, const cuuint64_t*, const cuuint32_t*, const cuuint32_t*,
    CUtensorMapInterleave, CUtensorMapSwizzle, CUtensorMapL2promotion,
    CUtensorMapFloatOOBfill);

extern "C" void kernel_launch(void* const* d_in, const int* in_sizes, int n_in,
                              void* d_out, int out_size)
{
    const int*   x     = (const int*)d_in[0];
    const float* emb   = (const float*)d_in[1];
    const float* Whh   = (const float*)d_in[2];
    const float* bhh   = (const float*)d_in[3];
    const float* Who   = (const float*)d_in[4];
    const float* bho   = (const float*)d_in[5];
    const float* gamma = (const float*)d_in[6];
    const float* beta  = (const float*)d_in[7];
    float* out = (float*)d_out;

    void* hsym = nullptr; cudaGetSymbolAddress(&hsym, g_h16);
    void* wsym = nullptr; cudaGetSymbolAddress(&wsym, g_Wh);
    PFN_tmap_enc enc = nullptr;
    cudaDriverEntryPointQueryResult qr;
    cudaGetDriverEntryPointByVersion("cuTensorMapEncodeTiled", (void**)&enc,
                                     12000, cudaEnableDefault, &qr);
    CUtensorMap mapH, mapW;
    {
        cuuint64_t dims[3] = {NHID, NB, 2};
        cuuint64_t strd[2] = {NHID * 2, (cuuint64_t)NB * NHID * 2};
        cuuint32_t box[3]  = {KCH, 128, 1};
        cuuint32_t es[3]   = {1, 1, 1};
        enc(&mapH, CU_TENSOR_MAP_DATA_TYPE_UINT16, 3, hsym, dims, strd, box, es,
            CU_TENSOR_MAP_INTERLEAVE_NONE, CU_TENSOR_MAP_SWIZZLE_128B,
            CU_TENSOR_MAP_L2_PROMOTION_L2_128B, CU_TENSOR_MAP_FLOAT_OOB_FILL_NONE);
    }
    {
        cuuint64_t dims[2] = {NHID, NHID};
        cuuint64_t strd[1] = {NHID * 2};
        cuuint32_t box[2]  = {KCH, 128};
        cuuint32_t es[2]   = {1, 1};
        enc(&mapW, CU_TENSOR_MAP_DATA_TYPE_UINT16, 2, wsym, dims, strd, box, es,
            CU_TENSOR_MAP_INTERLEAVE_NONE, CU_TENSOR_MAP_SWIZZLE_128B,
            CU_TENSOR_MAP_L2_PROMOTION_L2_128B, CU_TENSOR_MAP_FLOAT_OOB_FILL_NONE);
    }

    cudaFuncSetAttribute(k_persist, cudaFuncAttributeMaxDynamicSharedMemorySize,
                         SMEM_TOTAL);

    k_init<<<1024, 256>>>(Whh, emb, bhh, Who);
    k_persist<<<NBLK, NTHR, SMEM_TOTAL>>>(mapH, mapW, x, bho, gamma, beta, out);
}